// round 1
// baseline (speedup 1.0000x reference)
#include <cuda_runtime.h>
#include <math.h>

#define Bb   2
#define Tt   2048
#define Cc   2048
#define NH   16
#define NKV  4
#define HD   128
#define QDIM (NH * HD)    // 2048
#define KDIM (NKV * HD)   // 512
#define MROWS (Bb * Tt)   // 4096
#define ASTR 129          // odd shared-memory row stride -> conflict-free LDS

// Scratch (static device arrays; no allocation allowed)
__device__ float g_Q[(size_t)MROWS * QDIM];
__device__ float g_K[(size_t)MROWS * KDIM];
__device__ float g_V[(size_t)MROWS * KDIM];
__device__ float g_O[(size_t)MROWS * QDIM];

// ---------------------------------------------------------------------------
// SGEMM: C[M,N] = A[M,K] * B[K,N], all row-major. 128x128 tile, BK=16,
// 256 threads, 8x8 per thread with interleaved ownership (row = ty+16i,
// col = tx+16j) so shared reads are broadcast / fully coalesced.
// ---------------------------------------------------------------------------
__global__ __launch_bounds__(256) void sgemm128(const float* __restrict__ A,
                                                const float* __restrict__ Bm,
                                                float* __restrict__ Cm,
                                                int M, int N, int K)
{
    __shared__ float As[128][17];
    __shared__ float Bs[16][128];
    const int tid = threadIdx.x;
    const int tx = tid & 15, ty = tid >> 4;
    const int bm = blockIdx.y * 128, bn = blockIdx.x * 128;

    float acc[8][8];
#pragma unroll
    for (int i = 0; i < 8; i++)
#pragma unroll
        for (int j = 0; j < 8; j++) acc[i][j] = 0.0f;

    for (int k0 = 0; k0 < K; k0 += 16) {
#pragma unroll
        for (int i = 0; i < 8; i++) {
            int li = tid + i * 256;
            int m = li >> 4, kk = li & 15;
            As[m][kk] = A[(size_t)(bm + m) * K + (k0 + kk)];
        }
#pragma unroll
        for (int i = 0; i < 8; i++) {
            int li = tid + i * 256;
            int kk = li >> 7, n = li & 127;
            Bs[kk][n] = Bm[(size_t)(k0 + kk) * N + (bn + n)];
        }
        __syncthreads();
#pragma unroll
        for (int kk = 0; kk < 16; kk++) {
            float a[8], bv[8];
#pragma unroll
            for (int i = 0; i < 8; i++) a[i] = As[ty + 16 * i][kk];
#pragma unroll
            for (int j = 0; j < 8; j++) bv[j] = Bs[kk][tx + 16 * j];
#pragma unroll
            for (int i = 0; i < 8; i++)
#pragma unroll
                for (int j = 0; j < 8; j++) acc[i][j] += a[i] * bv[j];
        }
        __syncthreads();
    }
#pragma unroll
    for (int i = 0; i < 8; i++)
#pragma unroll
        for (int j = 0; j < 8; j++)
            Cm[(size_t)(bm + ty + 16 * i) * N + (bn + tx + 16 * j)] = acc[i][j];
}

// ---------------------------------------------------------------------------
// RoPE (in-place on Q and K). One thread per (token, head, freq) pair, which
// rotates elements d=f and d=f+64. Angle computed in double so our error is
// below the reference's own fp32 table rounding.
// ---------------------------------------------------------------------------
__global__ void rope_kernel(float* __restrict__ Qd, float* __restrict__ Kd)
{
    const int idx = blockIdx.x * blockDim.x + threadIdx.x;
    const int nq = MROWS * NH * 64;
    const int nk = MROWS * NKV * 64;
    if (idx >= nq + nk) return;

    float* ptr;
    int f, t;
    size_t base;
    if (idx < nq) {
        f = idx & 63;
        int h = (idx >> 6) & (NH - 1);
        int bt = idx >> 10;            // / (NH*64)
        t = bt & (Tt - 1);
        base = (size_t)bt * QDIM + h * HD;
        ptr = Qd;
    } else {
        int k = idx - nq;
        f = k & 63;
        int h = (k >> 6) & (NKV - 1);
        int bt = k >> 8;               // / (NKV*64)
        t = bt & (Tt - 1);
        base = (size_t)bt * KDIM + h * HD;
        ptr = Kd;
    }
    // timescale = 10000^(f/64)  ->  inv = exp(-f * ln(10000)/64)
    double inv = exp(-(double)f * 0.14391156831212787);
    double ang = (double)t * inv;
    float sn = (float)sin(ang);
    float cs = (float)cos(ang);
    float x1 = ptr[base + f];
    float x2 = ptr[base + f + 64];
    ptr[base + f]      = x1 * cs - x2 * sn;
    ptr[base + f + 64] = x2 * cs + x1 * sn;
}

// ---------------------------------------------------------------------------
// Flash attention with GQA, softcap, causal mask.
// Grid: (T/128, NH, B). 256 threads. Q tile 128x128 resident in smem; loop
// over causal K tiles of 128. V reuses K's smem buffer. Online softmax done
// by 128 row-threads. All smem reads conflict-free via ASTR=129 + interleaved
// thread ownership.
// ---------------------------------------------------------------------------
__global__ __launch_bounds__(256) void attn_kernel(const float* __restrict__ Qd,
                                                   const float* __restrict__ Kd,
                                                   const float* __restrict__ Vd,
                                                   float* __restrict__ Od)
{
    extern __shared__ float sm[];
    float* Qs    = sm;                    // [128][ASTR]
    float* KVs   = sm + 128 * ASTR;       // [128][ASTR] (K, then reused for V)
    float* Ps    = sm + 2 * 128 * ASTR;   // [128][ASTR] (S, then P)
    float* row_m = sm + 3 * 128 * ASTR;   // [128]
    float* row_l = row_m + 128;           // [128]
    float* row_c = row_l + 128;           // [128]

    const int tid = threadIdx.x;
    const int tx = tid & 15, ty = tid >> 4;
    const int qt = blockIdx.x, g = blockIdx.y, b = blockIdx.z;
    const int kvh = g & (NKV - 1);        // kv head = global head % 4
    const int q0 = qt * 128;

    // Load Q tile (float4, coalesced)
#pragma unroll
    for (int i = 0; i < 16; i++) {
        int li = tid + i * 256;
        int r = li >> 5, d4 = li & 31;
        const float4 v = *reinterpret_cast<const float4*>(
            Qd + (size_t)(b * Tt + q0 + r) * QDIM + g * HD + d4 * 4);
        float* dst = Qs + r * ASTR + d4 * 4;
        dst[0] = v.x; dst[1] = v.y; dst[2] = v.z; dst[3] = v.w;
    }
    if (tid < 128) { row_m[tid] = -INFINITY; row_l[tid] = 0.0f; }

    float acc[8][8];
#pragma unroll
    for (int i = 0; i < 8; i++)
#pragma unroll
        for (int j = 0; j < 8; j++) acc[i][j] = 0.0f;

    const float pre = 0.08838834764831843f * 0.02f;  // (1/sqrt(128)) / 50

    for (int kt = 0; kt <= qt; kt++) {
        const int k0 = kt * 128;
        __syncthreads();  // KVs free (prev PV done); also covers Q-load/stat init

        // Load K tile
#pragma unroll
        for (int i = 0; i < 16; i++) {
            int li = tid + i * 256;
            int r = li >> 5, d4 = li & 31;
            const float4 v = *reinterpret_cast<const float4*>(
                Kd + (size_t)(b * Tt + k0 + r) * KDIM + kvh * HD + d4 * 4);
            float* dst = KVs + r * ASTR + d4 * 4;
            dst[0] = v.x; dst[1] = v.y; dst[2] = v.z; dst[3] = v.w;
        }
        __syncthreads();

        // S = Q * K^T (8x8 per thread, interleaved)
        float s[8][8];
#pragma unroll
        for (int i = 0; i < 8; i++)
#pragma unroll
            for (int j = 0; j < 8; j++) s[i][j] = 0.0f;

#pragma unroll 4
        for (int d = 0; d < 128; d++) {
            float a[8], bv[8];
#pragma unroll
            for (int i = 0; i < 8; i++) a[i] = Qs[(ty + 16 * i) * ASTR + d];
#pragma unroll
            for (int j = 0; j < 8; j++) bv[j] = KVs[(tx + 16 * j) * ASTR + d];
#pragma unroll
            for (int i = 0; i < 8; i++)
#pragma unroll
                for (int j = 0; j < 8; j++) s[i][j] += a[i] * bv[j];
        }

        // scale + softcap + causal mask, write to Ps
        const bool diag = (kt == qt);
#pragma unroll
        for (int i = 0; i < 8; i++) {
            const int r = ty + 16 * i;
#pragma unroll
            for (int j = 0; j < 8; j++) {
                const int c = tx + 16 * j;
                float v = tanhf(s[i][j] * pre) * 50.0f;
                if (diag && c > r) v = -1e30f;
                Ps[r * ASTR + c] = v;
            }
        }
        __syncthreads();  // K reads done -> safe to overwrite KVs with V

        // Load V tile into KVs
#pragma unroll
        for (int i = 0; i < 16; i++) {
            int li = tid + i * 256;
            int r = li >> 5, d4 = li & 31;
            const float4 v = *reinterpret_cast<const float4*>(
                Vd + (size_t)(b * Tt + k0 + r) * KDIM + kvh * HD + d4 * 4);
            float* dst = KVs + r * ASTR + d4 * 4;
            dst[0] = v.x; dst[1] = v.y; dst[2] = v.z; dst[3] = v.w;
        }

        // Online softmax: one thread per row
        if (tid < 128) {
            const int r = tid;
            float m_old = row_m[r];
            float mx = m_old;
            for (int j = 0; j < 128; j++)
                mx = fmaxf(mx, Ps[r * ASTR + j]);
            float corr = __expf(m_old - mx);   // first tile: exp(-inf)=0
            float l = row_l[r] * corr;
            for (int j = 0; j < 128; j++) {
                float p = __expf(Ps[r * ASTR + j] - mx);
                Ps[r * ASTR + j] = p;
                l += p;
            }
            row_m[r] = mx;
            row_l[r] = l;
            row_c[r] = corr;
        }
        __syncthreads();  // V loaded AND softmax done

        // Rescale accumulators
#pragma unroll
        for (int i = 0; i < 8; i++) {
            float cr = row_c[ty + 16 * i];
#pragma unroll
            for (int j = 0; j < 8; j++) acc[i][j] *= cr;
        }

        // acc += P * V
#pragma unroll 4
        for (int j = 0; j < 128; j++) {
            float p[8], vv[8];
#pragma unroll
            for (int i = 0; i < 8; i++) p[i] = Ps[(ty + 16 * i) * ASTR + j];
#pragma unroll
            for (int c = 0; c < 8; c++) vv[c] = KVs[j * ASTR + tx + 16 * c];
#pragma unroll
            for (int i = 0; i < 8; i++)
#pragma unroll
                for (int c = 0; c < 8; c++) acc[i][c] += p[i] * vv[c];
        }
    }

    // Epilogue: normalize and store
#pragma unroll
    for (int i = 0; i < 8; i++) {
        const int r = ty + 16 * i;
        const float inv_l = 1.0f / row_l[r];
#pragma unroll
        for (int j = 0; j < 8; j++) {
            const int c = tx + 16 * j;
            Od[(size_t)(b * Tt + q0 + r) * QDIM + g * HD + c] = acc[i][j] * inv_l;
        }
    }
}

// ---------------------------------------------------------------------------
extern "C" void kernel_launch(void* const* d_in, const int* in_sizes, int n_in,
                              void* d_out, int out_size)
{
    const float* x  = (const float*)d_in[0];
    // d_in[1] = mask: known causal tril, handled analytically in attn_kernel
    const float* wq = (const float*)d_in[2];
    const float* wk = (const float*)d_in[3];
    const float* wv = (const float*)d_in[4];
    const float* wo = (const float*)d_in[5];
    float* out = (float*)d_out;

    float *Qp, *Kp, *Vp, *Op;
    cudaGetSymbolAddress((void**)&Qp, g_Q);
    cudaGetSymbolAddress((void**)&Kp, g_K);
    cudaGetSymbolAddress((void**)&Vp, g_V);
    cudaGetSymbolAddress((void**)&Op, g_O);

    // Projections
    sgemm128<<<dim3(QDIM / 128, MROWS / 128), 256>>>(x, wq, Qp, MROWS, QDIM, Cc);
    sgemm128<<<dim3(KDIM / 128, MROWS / 128), 256>>>(x, wk, Kp, MROWS, KDIM, Cc);
    sgemm128<<<dim3(KDIM / 128, MROWS / 128), 256>>>(x, wv, Vp, MROWS, KDIM, Cc);

    // RoPE on Q and K
    const int pairs = MROWS * (NH + NKV) * 64;
    rope_kernel<<<(pairs + 255) / 256, 256>>>(Qp, Kp);

    // Attention
    const int smem = (3 * 128 * ASTR + 3 * 128) * (int)sizeof(float);
    cudaFuncSetAttribute(attn_kernel, cudaFuncAttributeMaxDynamicSharedMemorySize, smem);
    attn_kernel<<<dim3(Tt / 128, NH, Bb), 256, smem>>>(Qp, Kp, Vp, Op);

    // Output projection -> d_out
    sgemm128<<<dim3(QDIM / 128, MROWS / 128), 256>>>(Op, wo, out, MROWS, QDIM, Cc);
}

// round 3
// speedup vs baseline: 2.3213x; 2.3213x over previous
#include <cuda_runtime.h>
#include <cuda_bf16.h>
#include <math.h>
#include <stdint.h>

#define Bb   2
#define Tt   2048
#define Cc   2048
#define NH   16
#define NKV  4
#define HD   128
#define QDIM (NH * HD)    // 2048
#define KDIM (NKV * HD)   // 512
#define MROWS (Bb * Tt)   // 4096
#define ASTR 129

// ------------------------- device scratch (no allocs allowed) --------------
__device__ float g_Q[(size_t)MROWS * QDIM];
__device__ float g_K[(size_t)MROWS * KDIM];
__device__ float g_V[(size_t)MROWS * KDIM];
__device__ float g_O[(size_t)MROWS * QDIM];
__device__ float2 g_rope[Tt * 64];

__device__ __nv_bfloat16 g_xhi[(size_t)MROWS * Cc];
__device__ __nv_bfloat16 g_xlo[(size_t)MROWS * Cc];
__device__ __nv_bfloat16 g_Ohi[(size_t)MROWS * QDIM];
__device__ __nv_bfloat16 g_Olo[(size_t)MROWS * QDIM];
__device__ __nv_bfloat16 g_wqT_hi[(size_t)QDIM * Cc];
__device__ __nv_bfloat16 g_wqT_lo[(size_t)QDIM * Cc];
__device__ __nv_bfloat16 g_wkT_hi[(size_t)KDIM * Cc];
__device__ __nv_bfloat16 g_wkT_lo[(size_t)KDIM * Cc];
__device__ __nv_bfloat16 g_wvT_hi[(size_t)KDIM * Cc];
__device__ __nv_bfloat16 g_wvT_lo[(size_t)KDIM * Cc];
__device__ __nv_bfloat16 g_woT_hi[(size_t)Cc * QDIM];
__device__ __nv_bfloat16 g_woT_lo[(size_t)Cc * QDIM];

// ------------------------- small PTX helpers (sm_80-era, base-target-safe) --
__device__ __forceinline__ uint32_t smem_u32(const void* p) {
    uint32_t a;
    asm("{ .reg .u64 t; cvta.to.shared.u64 t, %1; cvt.u32.u64 %0, t; }" : "=r"(a) : "l"(p));
    return a;
}
__device__ __forceinline__ void cp16(uint32_t saddr, const void* g) {
    asm volatile("cp.async.cg.shared.global [%0], [%1], 16;" :: "r"(saddr), "l"(g));
}
#define CP_COMMIT() asm volatile("cp.async.commit_group;" ::: "memory")
template <int N> __device__ __forceinline__ void cp_wait() {
    asm volatile("cp.async.wait_group %0;" :: "n"(N) : "memory");
}
__device__ __forceinline__ void ldsm4(uint32_t* r, uint32_t addr) {
    asm volatile("ldmatrix.sync.aligned.m8n8.x4.shared.b16 {%0,%1,%2,%3}, [%4];"
                 : "=r"(r[0]), "=r"(r[1]), "=r"(r[2]), "=r"(r[3]) : "r"(addr));
}
__device__ __forceinline__ void mma16816(float* d, const uint32_t* a, const uint32_t* b) {
    asm volatile("mma.sync.aligned.m16n8k16.row.col.f32.bf16.bf16.f32 "
                 "{%0,%1,%2,%3}, {%4,%5,%6,%7}, {%8,%9}, {%0,%1,%2,%3};"
                 : "+f"(d[0]), "+f"(d[1]), "+f"(d[2]), "+f"(d[3])
                 : "r"(a[0]), "r"(a[1]), "r"(a[2]), "r"(a[3]), "r"(b[0]), "r"(b[1]));
}
__device__ __forceinline__ uint32_t swz128(uint32_t o) { return o ^ ((o >> 3) & 0x70); }

// ------------------------- prep kernels ------------------------------------
__global__ void split_bf16(const float* __restrict__ src,
                           __nv_bfloat16* __restrict__ hi,
                           __nv_bfloat16* __restrict__ lo, int n4) {
    int i = blockIdx.x * blockDim.x + threadIdx.x;
    if (i >= n4) return;
    float4 v = ((const float4*)src)[i];
    __nv_bfloat16 h0 = __float2bfloat16(v.x), h1 = __float2bfloat16(v.y);
    __nv_bfloat16 h2 = __float2bfloat16(v.z), h3 = __float2bfloat16(v.w);
    __nv_bfloat162* hp = (__nv_bfloat162*)hi;
    __nv_bfloat162* lp = (__nv_bfloat162*)lo;
    hp[i * 2]     = __nv_bfloat162(h0, h1);
    hp[i * 2 + 1] = __nv_bfloat162(h2, h3);
    lp[i * 2]     = __nv_bfloat162(__float2bfloat16(v.x - __bfloat162float(h0)),
                                   __float2bfloat16(v.y - __bfloat162float(h1)));
    lp[i * 2 + 1] = __nv_bfloat162(__float2bfloat16(v.z - __bfloat162float(h2)),
                                   __float2bfloat16(v.w - __bfloat162float(h3)));
}

// src [K,N] row-major fp32 -> hi/lo [N,K] bf16 (transposed, K contiguous)
__global__ void transpose_split(const float* __restrict__ src,
                                __nv_bfloat16* __restrict__ hi,
                                __nv_bfloat16* __restrict__ lo, int K, int N) {
    __shared__ float t[32][33];
    const int k0 = blockIdx.y * 32, n0 = blockIdx.x * 32;
    const int tx = threadIdx.x, ty = threadIdx.y;  // 32x8
#pragma unroll
    for (int i = 0; i < 4; i++)
        t[ty + 8 * i][tx] = src[(size_t)(k0 + ty + 8 * i) * N + n0 + tx];
    __syncthreads();
#pragma unroll
    for (int i = 0; i < 4; i++) {
        float v = t[tx][ty + 8 * i];
        __nv_bfloat16 h = __float2bfloat16(v);
        size_t o = (size_t)(n0 + ty + 8 * i) * K + k0 + tx;
        hi[o] = h;
        lo[o] = __float2bfloat16(v - __bfloat162float(h));
    }
}

// ------------------------- HMMA split-precision GEMM ------------------------
// C[M,N] fp32 = A * B^T ; Ahi/Alo [M,K] bf16 K-contig, Bhi/Blo [N,K] bf16.
// CTA tile 128x128, K-chunk 64 (128B rows, SW128), cp.async double buffer.
// 8 warps: warp (wm = wid>>1 in 0..3) x (wn = wid&1 in 0..1), warp tile 32x64.
#define GSMEM (2 * 65536 + 128)
__global__ __launch_bounds__(256) void gemm_hmma(
    const __nv_bfloat16* __restrict__ Ahi, const __nv_bfloat16* __restrict__ Alo,
    const __nv_bfloat16* __restrict__ Bhi, const __nv_bfloat16* __restrict__ Blo,
    float* __restrict__ C, int Ndim, int Kdim)
{
    extern __shared__ char smraw[];
    const uint32_t sb = (smem_u32(smraw) + 127) & ~127u;
    const int tid = threadIdx.x;
    const int lane = tid & 31, wid = tid >> 5;
    const int wm = wid >> 1, wn = wid & 1;
    const int bm = blockIdx.y * 128, bn = blockIdx.x * 128;

    float acc[2][8][4];
#pragma unroll
    for (int i = 0; i < 2; i++)
#pragma unroll
        for (int t = 0; t < 8; t++)
#pragma unroll
            for (int e = 0; e < 4; e++) acc[i][t][e] = 0.0f;

    const int nch = Kdim >> 6;

    // prefetch one K-chunk into stage (ch&1)
    auto prefetch = [&](int ch) {
        const uint32_t st = sb + (ch & 1) * 65536;
        const int kc = ch << 6;
#pragma unroll
        for (int q = 0; q < 4; q++) {
            int idx = tid + q * 256;
            int r = idx >> 3, u = idx & 7;
            uint32_t so = swz128((uint32_t)(r * 128 + u * 16));
            const size_t ga = (size_t)(bm + r) * Kdim + kc + u * 8;
            const size_t gb = (size_t)(bn + r) * Kdim + kc + u * 8;
            cp16(st + so,         Ahi + ga);
            cp16(st + 16384 + so, Alo + ga);
            cp16(st + 32768 + so, Bhi + gb);
            cp16(st + 49152 + so, Blo + gb);
        }
        CP_COMMIT();
    };

    prefetch(0);
    // ldmatrix lane address components (constant over chunks)
    const uint32_t arow = wm * 32 + (lane & 15);
    const uint32_t acb  = ((uint32_t)(lane >> 4)) << 4;         // A k-half byte
    const uint32_t brow = wn * 64 + (lane & 7) + (((uint32_t)(lane >> 4)) << 3);
    const uint32_t bcb  = (((uint32_t)(lane >> 3)) & 1u) << 4;  // B k-half byte

    for (int ch = 0; ch < nch; ch++) {
        if (ch + 1 < nch) { prefetch(ch + 1); cp_wait<1>(); }
        else              { cp_wait<0>(); }
        __syncthreads();
        const uint32_t st = sb + (ch & 1) * 65536;
#pragma unroll
        for (int s = 0; s < 4; s++) {
            const uint32_t kb = s * 32;
            uint32_t ah[2][4], al[2][4], bh[4][4], bl[4][4];
#pragma unroll
            for (int i = 0; i < 2; i++) {
                uint32_t off = swz128((arow + i * 16) * 128 + kb + acb);
                ldsm4(ah[i], st + off);
                ldsm4(al[i], st + 16384 + off);
            }
#pragma unroll
            for (int j = 0; j < 4; j++) {
                uint32_t off = swz128((brow + j * 16) * 128 + kb + bcb);
                ldsm4(bh[j], st + 32768 + off);
                ldsm4(bl[j], st + 49152 + off);
            }
#pragma unroll
            for (int i = 0; i < 2; i++)
#pragma unroll
                for (int t = 0; t < 8; t++) {
                    const uint32_t* bhp = &bh[t >> 1][(t & 1) * 2];
                    const uint32_t* blp = &bl[t >> 1][(t & 1) * 2];
                    mma16816(acc[i][t], ah[i], bhp);
                    mma16816(acc[i][t], ah[i], blp);
                    mma16816(acc[i][t], al[i], bhp);
                }
        }
        __syncthreads();
    }

    // epilogue: d0,d1 -> (row, col..col+1); d2,d3 -> (row+8, ...)
#pragma unroll
    for (int i = 0; i < 2; i++) {
        const int r0 = bm + wm * 32 + i * 16 + (lane >> 2);
#pragma unroll
        for (int t = 0; t < 8; t++) {
            const int c = bn + wn * 64 + t * 8 + (lane & 3) * 2;
            *(float2*)(C + (size_t)r0 * Ndim + c) = make_float2(acc[i][t][0], acc[i][t][1]);
            *(float2*)(C + (size_t)(r0 + 8) * Ndim + c) = make_float2(acc[i][t][2], acc[i][t][3]);
        }
    }
}

// ------------------------- RoPE --------------------------------------------
__global__ void rope_table_kernel() {
    const int i = blockIdx.x * blockDim.x + threadIdx.x;
    if (i >= Tt * 64) return;
    const int t = i >> 6, f = i & 63;
    double inv = exp(-(double)f * 0.14391156831212787);  // ln(10000)/64
    double a = (double)t * inv;
    g_rope[i] = make_float2((float)sin(a), (float)cos(a));
}

__global__ void rope_apply(float* __restrict__ Qd, float* __restrict__ Kd) {
    const int idx = blockIdx.x * blockDim.x + threadIdx.x;
    const int nq = MROWS * NH * 64;
    const int nk = MROWS * NKV * 64;
    if (idx >= nq + nk) return;
    float* ptr; int f, t; size_t base;
    if (idx < nq) {
        f = idx & 63;
        int h = (idx >> 6) & (NH - 1);
        int bt = idx >> 10;
        t = bt & (Tt - 1);
        base = (size_t)bt * QDIM + h * HD;
        ptr = Qd;
    } else {
        int k = idx - nq;
        f = k & 63;
        int h = (k >> 6) & (NKV - 1);
        int bt = k >> 8;
        t = bt & (Tt - 1);
        base = (size_t)bt * KDIM + h * HD;
        ptr = Kd;
    }
    const float2 sc = g_rope[t * 64 + f];
    const float x1 = ptr[base + f];
    const float x2 = ptr[base + f + 64];
    ptr[base + f]      = x1 * sc.y - x2 * sc.x;
    ptr[base + f + 64] = x2 * sc.y + x1 * sc.x;
}

// ------------------------- flash attention (FFMA, validated) ---------------
__global__ __launch_bounds__(256) void attn_kernel(const float* __restrict__ Qd,
                                                   const float* __restrict__ Kd,
                                                   const float* __restrict__ Vd,
                                                   float* __restrict__ Od)
{
    extern __shared__ float sm[];
    float* Qs    = sm;
    float* KVs   = sm + 128 * ASTR;
    float* Ps    = sm + 2 * 128 * ASTR;
    float* row_m = sm + 3 * 128 * ASTR;
    float* row_l = row_m + 128;
    float* row_c = row_l + 128;

    const int tid = threadIdx.x;
    const int tx = tid & 15, ty = tid >> 4;
    const int qt = blockIdx.x, g = blockIdx.y, b = blockIdx.z;
    const int kvh = g & (NKV - 1);
    const int q0 = qt * 128;

#pragma unroll
    for (int i = 0; i < 16; i++) {
        int li = tid + i * 256;
        int r = li >> 5, d4 = li & 31;
        const float4 v = *reinterpret_cast<const float4*>(
            Qd + (size_t)(b * Tt + q0 + r) * QDIM + g * HD + d4 * 4);
        float* dst = Qs + r * ASTR + d4 * 4;
        dst[0] = v.x; dst[1] = v.y; dst[2] = v.z; dst[3] = v.w;
    }
    if (tid < 128) { row_m[tid] = -INFINITY; row_l[tid] = 0.0f; }

    float acc[8][8];
#pragma unroll
    for (int i = 0; i < 8; i++)
#pragma unroll
        for (int j = 0; j < 8; j++) acc[i][j] = 0.0f;

    const float pre = 0.08838834764831843f * 0.02f;

    for (int kt = 0; kt <= qt; kt++) {
        const int k0 = kt * 128;
        __syncthreads();
#pragma unroll
        for (int i = 0; i < 16; i++) {
            int li = tid + i * 256;
            int r = li >> 5, d4 = li & 31;
            const float4 v = *reinterpret_cast<const float4*>(
                Kd + (size_t)(b * Tt + k0 + r) * KDIM + kvh * HD + d4 * 4);
            float* dst = KVs + r * ASTR + d4 * 4;
            dst[0] = v.x; dst[1] = v.y; dst[2] = v.z; dst[3] = v.w;
        }
        __syncthreads();

        float s[8][8];
#pragma unroll
        for (int i = 0; i < 8; i++)
#pragma unroll
            for (int j = 0; j < 8; j++) s[i][j] = 0.0f;
#pragma unroll 4
        for (int d = 0; d < 128; d++) {
            float a[8], bv[8];
#pragma unroll
            for (int i = 0; i < 8; i++) a[i] = Qs[(ty + 16 * i) * ASTR + d];
#pragma unroll
            for (int j = 0; j < 8; j++) bv[j] = KVs[(tx + 16 * j) * ASTR + d];
#pragma unroll
            for (int i = 0; i < 8; i++)
#pragma unroll
                for (int j = 0; j < 8; j++) s[i][j] += a[i] * bv[j];
        }

        const bool diag = (kt == qt);
#pragma unroll
        for (int i = 0; i < 8; i++) {
            const int r = ty + 16 * i;
#pragma unroll
            for (int j = 0; j < 8; j++) {
                const int c = tx + 16 * j;
                float v = tanhf(s[i][j] * pre) * 50.0f;
                if (diag && c > r) v = -1e30f;
                Ps[r * ASTR + c] = v;
            }
        }
        __syncthreads();

#pragma unroll
        for (int i = 0; i < 16; i++) {
            int li = tid + i * 256;
            int r = li >> 5, d4 = li & 31;
            const float4 v = *reinterpret_cast<const float4*>(
                Vd + (size_t)(b * Tt + k0 + r) * KDIM + kvh * HD + d4 * 4);
            float* dst = KVs + r * ASTR + d4 * 4;
            dst[0] = v.x; dst[1] = v.y; dst[2] = v.z; dst[3] = v.w;
        }

        if (tid < 128) {
            const int r = tid;
            float m_old = row_m[r];
            float mx = m_old;
            for (int j = 0; j < 128; j++)
                mx = fmaxf(mx, Ps[r * ASTR + j]);
            float corr = __expf(m_old - mx);
            float l = row_l[r] * corr;
            for (int j = 0; j < 128; j++) {
                float p = __expf(Ps[r * ASTR + j] - mx);
                Ps[r * ASTR + j] = p;
                l += p;
            }
            row_m[r] = mx;
            row_l[r] = l;
            row_c[r] = corr;
        }
        __syncthreads();

#pragma unroll
        for (int i = 0; i < 8; i++) {
            float cr = row_c[ty + 16 * i];
#pragma unroll
            for (int j = 0; j < 8; j++) acc[i][j] *= cr;
        }
#pragma unroll 4
        for (int j = 0; j < 128; j++) {
            float p[8], vv[8];
#pragma unroll
            for (int i = 0; i < 8; i++) p[i] = Ps[(ty + 16 * i) * ASTR + j];
#pragma unroll
            for (int c = 0; c < 8; c++) vv[c] = KVs[j * ASTR + tx + 16 * c];
#pragma unroll
            for (int i = 0; i < 8; i++)
#pragma unroll
                for (int c = 0; c < 8; c++) acc[i][c] += p[i] * vv[c];
        }
    }

#pragma unroll
    for (int i = 0; i < 8; i++) {
        const int r = ty + 16 * i;
        const float inv_l = 1.0f / row_l[r];
#pragma unroll
        for (int j = 0; j < 8; j++) {
            const int c = tx + 16 * j;
            Od[(size_t)(b * Tt + q0 + r) * QDIM + g * HD + c] = acc[i][j] * inv_l;
        }
    }
}

// ---------------------------------------------------------------------------
extern "C" void kernel_launch(void* const* d_in, const int* in_sizes, int n_in,
                              void* d_out, int out_size)
{
    const float* x  = (const float*)d_in[0];
    const float* wq = (const float*)d_in[2];
    const float* wk = (const float*)d_in[3];
    const float* wv = (const float*)d_in[4];
    const float* wo = (const float*)d_in[5];
    float* out = (float*)d_out;

    float *Qp, *Kp, *Vp, *Op;
    cudaGetSymbolAddress((void**)&Qp, g_Q);
    cudaGetSymbolAddress((void**)&Kp, g_K);
    cudaGetSymbolAddress((void**)&Vp, g_V);
    cudaGetSymbolAddress((void**)&Op, g_O);
    __nv_bfloat16 *xhi, *xlo, *Ohi, *Olo;
    __nv_bfloat16 *wqh, *wql, *wkh, *wkl, *wvh, *wvl, *woh, *wol;
    cudaGetSymbolAddress((void**)&xhi, g_xhi);
    cudaGetSymbolAddress((void**)&xlo, g_xlo);
    cudaGetSymbolAddress((void**)&Ohi, g_Ohi);
    cudaGetSymbolAddress((void**)&Olo, g_Olo);
    cudaGetSymbolAddress((void**)&wqh, g_wqT_hi);
    cudaGetSymbolAddress((void**)&wql, g_wqT_lo);
    cudaGetSymbolAddress((void**)&wkh, g_wkT_hi);
    cudaGetSymbolAddress((void**)&wkl, g_wkT_lo);
    cudaGetSymbolAddress((void**)&wvh, g_wvT_hi);
    cudaGetSymbolAddress((void**)&wvl, g_wvT_lo);
    cudaGetSymbolAddress((void**)&woh, g_woT_hi);
    cudaGetSymbolAddress((void**)&wol, g_woT_lo);

    // ---- prep: split x, transpose+split weights
    {
        int n4 = MROWS * Cc / 4;
        split_bf16<<<(n4 + 255) / 256, 256>>>(x, xhi, xlo, n4);
    }
    transpose_split<<<dim3(QDIM / 32, Cc / 32), dim3(32, 8)>>>(wq, wqh, wql, Cc, QDIM);
    transpose_split<<<dim3(KDIM / 32, Cc / 32), dim3(32, 8)>>>(wk, wkh, wkl, Cc, KDIM);
    transpose_split<<<dim3(KDIM / 32, Cc / 32), dim3(32, 8)>>>(wv, wvh, wvl, Cc, KDIM);
    transpose_split<<<dim3(Cc / 32, QDIM / 32), dim3(32, 8)>>>(wo, woh, wol, QDIM, Cc);

    // ---- projections (HMMA split)
    cudaFuncSetAttribute(gemm_hmma, cudaFuncAttributeMaxDynamicSharedMemorySize, GSMEM);
    gemm_hmma<<<dim3(QDIM / 128, MROWS / 128), 256, GSMEM>>>(xhi, xlo, wqh, wql, Qp, QDIM, Cc);
    gemm_hmma<<<dim3(KDIM / 128, MROWS / 128), 256, GSMEM>>>(xhi, xlo, wkh, wkl, Kp, KDIM, Cc);
    gemm_hmma<<<dim3(KDIM / 128, MROWS / 128), 256, GSMEM>>>(xhi, xlo, wvh, wvl, Vp, KDIM, Cc);

    // ---- RoPE (table + apply)
    rope_table_kernel<<<(Tt * 64 + 255) / 256, 256>>>();
    const int pairs = MROWS * (NH + NKV) * 64;
    rope_apply<<<(pairs + 255) / 256, 256>>>(Qp, Kp);

    // ---- attention (FFMA)
    const int smem = (3 * 128 * ASTR + 3 * 128) * (int)sizeof(float);
    cudaFuncSetAttribute(attn_kernel, cudaFuncAttributeMaxDynamicSharedMemorySize, smem);
    attn_kernel<<<dim3(Tt / 128, NH, Bb), 256, smem>>>(Qp, Kp, Vp, Op);

    // ---- output projection (HMMA split)
    {
        int n4 = MROWS * QDIM / 4;
        split_bf16<<<(n4 + 255) / 256, 256>>>(Op, Ohi, Olo, n4);
    }
    gemm_hmma<<<dim3(QDIM / 128, MROWS / 128), 256, GSMEM>>>(Ohi, Olo, woh, wol, out, QDIM, Cc);
}

// round 4
// speedup vs baseline: 4.1776x; 1.7996x over previous
#include <cuda_runtime.h>
#include <cuda_bf16.h>
#include <math.h>
#include <stdint.h>

#define Bb   2
#define Tt   2048
#define Cc   2048
#define NH   16
#define NKV  4
#define HD   128
#define QDIM (NH * HD)    // 2048
#define KDIM (NKV * HD)   // 512
#define MROWS (Bb * Tt)   // 4096

// ------------------------- device scratch (no allocs allowed) --------------
__device__ float g_Q[(size_t)MROWS * QDIM];
__device__ float g_K[(size_t)MROWS * KDIM];
__device__ float g_V[(size_t)MROWS * KDIM];
__device__ float2 g_rope[Tt * 64];

__device__ __nv_bfloat16 g_xhi[(size_t)MROWS * Cc];   // x split; reused as Q hi after projections
__device__ __nv_bfloat16 g_xlo[(size_t)MROWS * Cc];   // x split; reused as Q lo
__device__ __nv_bfloat16 g_Khi[(size_t)MROWS * KDIM];
__device__ __nv_bfloat16 g_Klo[(size_t)MROWS * KDIM];
__device__ __nv_bfloat16 g_Vhi[(size_t)MROWS * KDIM];
__device__ __nv_bfloat16 g_Vlo[(size_t)MROWS * KDIM];
__device__ __nv_bfloat16 g_Ohi[(size_t)MROWS * QDIM];
__device__ __nv_bfloat16 g_Olo[(size_t)MROWS * QDIM];
__device__ __nv_bfloat16 g_wqT_hi[(size_t)QDIM * Cc];
__device__ __nv_bfloat16 g_wqT_lo[(size_t)QDIM * Cc];
__device__ __nv_bfloat16 g_wkT_hi[(size_t)KDIM * Cc];
__device__ __nv_bfloat16 g_wkT_lo[(size_t)KDIM * Cc];
__device__ __nv_bfloat16 g_wvT_hi[(size_t)KDIM * Cc];
__device__ __nv_bfloat16 g_wvT_lo[(size_t)KDIM * Cc];
__device__ __nv_bfloat16 g_woT_hi[(size_t)Cc * QDIM];
__device__ __nv_bfloat16 g_woT_lo[(size_t)Cc * QDIM];

// ------------------------- PTX helpers (sm_80-era, base-target-safe) -------
__device__ __forceinline__ uint32_t smem_u32(const void* p) {
    uint32_t a;
    asm("{ .reg .u64 t; cvta.to.shared.u64 t, %1; cvt.u32.u64 %0, t; }" : "=r"(a) : "l"(p));
    return a;
}
__device__ __forceinline__ void cp16(uint32_t saddr, const void* g) {
    asm volatile("cp.async.cg.shared.global [%0], [%1], 16;" :: "r"(saddr), "l"(g));
}
#define CP_COMMIT() asm volatile("cp.async.commit_group;" ::: "memory")
template <int N> __device__ __forceinline__ void cp_wait() {
    asm volatile("cp.async.wait_group %0;" :: "n"(N) : "memory");
}
__device__ __forceinline__ void ldsm4(uint32_t* r, uint32_t addr) {
    asm volatile("ldmatrix.sync.aligned.m8n8.x4.shared.b16 {%0,%1,%2,%3}, [%4];"
                 : "=r"(r[0]), "=r"(r[1]), "=r"(r[2]), "=r"(r[3]) : "r"(addr));
}
__device__ __forceinline__ void ldsm4t(uint32_t* r, uint32_t addr) {
    asm volatile("ldmatrix.sync.aligned.m8n8.x4.trans.shared.b16 {%0,%1,%2,%3}, [%4];"
                 : "=r"(r[0]), "=r"(r[1]), "=r"(r[2]), "=r"(r[3]) : "r"(addr));
}
__device__ __forceinline__ void mma16816(float* d, const uint32_t* a, const uint32_t* b) {
    asm volatile("mma.sync.aligned.m16n8k16.row.col.f32.bf16.bf16.f32 "
                 "{%0,%1,%2,%3}, {%4,%5,%6,%7}, {%8,%9}, {%0,%1,%2,%3};"
                 : "+f"(d[0]), "+f"(d[1]), "+f"(d[2]), "+f"(d[3])
                 : "r"(a[0]), "r"(a[1]), "r"(a[2]), "r"(a[3]), "r"(b[0]), "r"(b[1]));
}
__device__ __forceinline__ uint32_t swz128(uint32_t o) { return o ^ ((o >> 3) & 0x70); }

// ------------------------- prep kernels ------------------------------------
__global__ void split_bf16(const float* __restrict__ src,
                           __nv_bfloat16* __restrict__ hi,
                           __nv_bfloat16* __restrict__ lo, int n4) {
    int i = blockIdx.x * blockDim.x + threadIdx.x;
    if (i >= n4) return;
    float4 v = ((const float4*)src)[i];
    __nv_bfloat16 h0 = __float2bfloat16(v.x), h1 = __float2bfloat16(v.y);
    __nv_bfloat16 h2 = __float2bfloat16(v.z), h3 = __float2bfloat16(v.w);
    __nv_bfloat162* hp = (__nv_bfloat162*)hi;
    __nv_bfloat162* lp = (__nv_bfloat162*)lo;
    hp[i * 2]     = __nv_bfloat162(h0, h1);
    hp[i * 2 + 1] = __nv_bfloat162(h2, h3);
    lp[i * 2]     = __nv_bfloat162(__float2bfloat16(v.x - __bfloat162float(h0)),
                                   __float2bfloat16(v.y - __bfloat162float(h1)));
    lp[i * 2 + 1] = __nv_bfloat162(__float2bfloat16(v.z - __bfloat162float(h2)),
                                   __float2bfloat16(v.w - __bfloat162float(h3)));
}

// src [K,N] row-major fp32 -> hi/lo [N,K] bf16 (transposed, K contiguous)
__global__ void transpose_split(const float* __restrict__ src,
                                __nv_bfloat16* __restrict__ hi,
                                __nv_bfloat16* __restrict__ lo, int K, int N) {
    __shared__ float t[32][33];
    const int k0 = blockIdx.y * 32, n0 = blockIdx.x * 32;
    const int tx = threadIdx.x, ty = threadIdx.y;  // 32x8
#pragma unroll
    for (int i = 0; i < 4; i++)
        t[ty + 8 * i][tx] = src[(size_t)(k0 + ty + 8 * i) * N + n0 + tx];
    __syncthreads();
#pragma unroll
    for (int i = 0; i < 4; i++) {
        float v = t[tx][ty + 8 * i];
        __nv_bfloat16 h = __float2bfloat16(v);
        size_t o = (size_t)(n0 + ty + 8 * i) * K + k0 + tx;
        hi[o] = h;
        lo[o] = __float2bfloat16(v - __bfloat162float(h));
    }
}

// ------------------------- HMMA split-precision GEMM ------------------------
#define GSMEM (2 * 65536 + 128)
__global__ __launch_bounds__(256) void gemm_hmma(
    const __nv_bfloat16* __restrict__ Ahi, const __nv_bfloat16* __restrict__ Alo,
    const __nv_bfloat16* __restrict__ Bhi, const __nv_bfloat16* __restrict__ Blo,
    float* __restrict__ C, int Ndim, int Kdim)
{
    extern __shared__ char smraw[];
    const uint32_t sb = (smem_u32(smraw) + 127) & ~127u;
    const int tid = threadIdx.x;
    const int lane = tid & 31, wid = tid >> 5;
    const int wm = wid >> 1, wn = wid & 1;
    const int bm = blockIdx.y * 128, bn = blockIdx.x * 128;

    float acc[2][8][4];
#pragma unroll
    for (int i = 0; i < 2; i++)
#pragma unroll
        for (int t = 0; t < 8; t++)
#pragma unroll
            for (int e = 0; e < 4; e++) acc[i][t][e] = 0.0f;

    const int nch = Kdim >> 6;

    auto prefetch = [&](int ch) {
        const uint32_t st = sb + (ch & 1) * 65536;
        const int kc = ch << 6;
#pragma unroll
        for (int q = 0; q < 4; q++) {
            int idx = tid + q * 256;
            int r = idx >> 3, u = idx & 7;
            uint32_t so = swz128((uint32_t)(r * 128 + u * 16));
            const size_t ga = (size_t)(bm + r) * Kdim + kc + u * 8;
            const size_t gb = (size_t)(bn + r) * Kdim + kc + u * 8;
            cp16(st + so,         Ahi + ga);
            cp16(st + 16384 + so, Alo + ga);
            cp16(st + 32768 + so, Bhi + gb);
            cp16(st + 49152 + so, Blo + gb);
        }
        CP_COMMIT();
    };

    prefetch(0);
    const uint32_t arow = wm * 32 + (lane & 15);
    const uint32_t acb  = ((uint32_t)(lane >> 4)) << 4;
    const uint32_t brow = wn * 64 + (lane & 7) + (((uint32_t)(lane >> 4)) << 3);
    const uint32_t bcb  = (((uint32_t)(lane >> 3)) & 1u) << 4;

    for (int ch = 0; ch < nch; ch++) {
        if (ch + 1 < nch) { prefetch(ch + 1); cp_wait<1>(); }
        else              { cp_wait<0>(); }
        __syncthreads();
        const uint32_t st = sb + (ch & 1) * 65536;
#pragma unroll
        for (int s = 0; s < 4; s++) {
            const uint32_t kb = s * 32;
            uint32_t ah[2][4], al[2][4], bh[4][4], bl[4][4];
#pragma unroll
            for (int i = 0; i < 2; i++) {
                uint32_t off = swz128((arow + i * 16) * 128 + kb + acb);
                ldsm4(ah[i], st + off);
                ldsm4(al[i], st + 16384 + off);
            }
#pragma unroll
            for (int j = 0; j < 4; j++) {
                uint32_t off = swz128((brow + j * 16) * 128 + kb + bcb);
                ldsm4(bh[j], st + 32768 + off);
                ldsm4(bl[j], st + 49152 + off);
            }
#pragma unroll
            for (int i = 0; i < 2; i++)
#pragma unroll
                for (int t = 0; t < 8; t++) {
                    const uint32_t* bhp = &bh[t >> 1][(t & 1) * 2];
                    const uint32_t* blp = &bl[t >> 1][(t & 1) * 2];
                    mma16816(acc[i][t], ah[i], bhp);
                    mma16816(acc[i][t], ah[i], blp);
                    mma16816(acc[i][t], al[i], bhp);
                }
        }
        __syncthreads();
    }

#pragma unroll
    for (int i = 0; i < 2; i++) {
        const int r0 = bm + wm * 32 + i * 16 + (lane >> 2);
#pragma unroll
        for (int t = 0; t < 8; t++) {
            const int c = bn + wn * 64 + t * 8 + (lane & 3) * 2;
            *(float2*)(C + (size_t)r0 * Ndim + c) = make_float2(acc[i][t][0], acc[i][t][1]);
            *(float2*)(C + (size_t)(r0 + 8) * Ndim + c) = make_float2(acc[i][t][2], acc[i][t][3]);
        }
    }
}

// ------------------------- RoPE table + fused rope/split -------------------
__global__ void rope_table_kernel() {
    const int i = blockIdx.x * blockDim.x + threadIdx.x;
    if (i >= Tt * 64) return;
    const int t = i >> 6, f = i & 63;
    double inv = exp(-(double)f * 0.14391156831212787);  // ln(10000)/64
    double a = (double)t * inv;
    g_rope[i] = make_float2((float)sin(a), (float)cos(a));
}

__global__ void rope_split(const float* __restrict__ Qf, const float* __restrict__ Kf,
                           __nv_bfloat16* __restrict__ Qhi, __nv_bfloat16* __restrict__ Qlo,
                           __nv_bfloat16* __restrict__ Khi, __nv_bfloat16* __restrict__ Klo)
{
    const int idx = blockIdx.x * blockDim.x + threadIdx.x;
    const int nq = MROWS * NH * 64;
    const int nk = MROWS * NKV * 64;
    if (idx >= nq + nk) return;
    const float* src; __nv_bfloat16 *dhi, *dlo;
    int f, t; size_t base;
    if (idx < nq) {
        f = idx & 63;
        int h = (idx >> 6) & (NH - 1);
        int bt = idx >> 10;
        t = bt & (Tt - 1);
        base = (size_t)bt * QDIM + h * HD;
        src = Qf; dhi = Qhi; dlo = Qlo;
    } else {
        int k = idx - nq;
        f = k & 63;
        int h = (k >> 6) & (NKV - 1);
        int bt = k >> 8;
        t = bt & (Tt - 1);
        base = (size_t)bt * KDIM + h * HD;
        src = Kf; dhi = Khi; dlo = Klo;
    }
    const float2 sc = g_rope[t * 64 + f];
    const float x1 = src[base + f];
    const float x2 = src[base + f + 64];
    const float r1 = x1 * sc.y - x2 * sc.x;
    const float r2 = x2 * sc.y + x1 * sc.x;
    __nv_bfloat16 h1 = __float2bfloat16(r1);
    __nv_bfloat16 h2 = __float2bfloat16(r2);
    dhi[base + f]      = h1;
    dhi[base + f + 64] = h2;
    dlo[base + f]      = __float2bfloat16(r1 - __bfloat162float(h1));
    dlo[base + f + 64] = __float2bfloat16(r2 - __bfloat162float(h2));
}

// ------------------------- HMMA flash attention ----------------------------
// smem layout (bytes)
#define SQ_HI 0
#define SQ_LO 32768
#define SK_HI 65536
#define SK_LO 98304
#define SP_HI 131072
#define SP_LO 163840
#define SRED  196608
#define ATT_SMEM (SRED + 896 * 4)   // + row_m/l/c[128], pmax[256], psum[256]

__global__ __launch_bounds__(256) void attn_hmma(
    const __nv_bfloat16* __restrict__ Qhi, const __nv_bfloat16* __restrict__ Qlo,
    const __nv_bfloat16* __restrict__ Khi, const __nv_bfloat16* __restrict__ Klo,
    const __nv_bfloat16* __restrict__ Vhi, const __nv_bfloat16* __restrict__ Vlo,
    __nv_bfloat16* __restrict__ Ohi, __nv_bfloat16* __restrict__ Olo)
{
    extern __shared__ char smraw[];
    const uint32_t sb = smem_u32(smraw);
    float* row_m = (float*)(smraw + SRED);
    float* row_l = row_m + 128;
    float* row_c = row_l + 128;
    float* pmax  = row_c + 128;   // [2][128]
    float* psum  = pmax + 256;    // [2][128]

    const int tid = threadIdx.x, lane = tid & 31, wid = tid >> 5;
    const int wm = wid >> 1, wn = wid & 1;
    const int qt = (int)gridDim.x - 1 - (int)blockIdx.x;   // big tiles first
    const int g = blockIdx.y, b = blockIdx.z;
    const int kvh = g & (NKV - 1);
    const int q0 = qt * 128;
    const size_t qrow = (size_t)(b * Tt + q0);

    // Q tile load (hi+lo)
    {
        const __nv_bfloat16* gh = Qhi + qrow * QDIM + g * HD;
        const __nv_bfloat16* gl = Qlo + qrow * QDIM + g * HD;
#pragma unroll
        for (int q = 0; q < 8; q++) {
            int idx = tid + q * 256;
            int r = idx >> 4, u = idx & 15;
            uint32_t so = ((uint32_t)(u >> 3) << 14) + swz128((uint32_t)(r * 128 + (u & 7) * 16));
            cp16(sb + SQ_HI + so, gh + (size_t)r * QDIM + u * 8);
            cp16(sb + SQ_LO + so, gl + (size_t)r * QDIM + u * 8);
        }
        CP_COMMIT();
    }
    if (tid < 128) { row_m[tid] = -INFINITY; row_l[tid] = 0.0f; }

    float o[2][8][4];
#pragma unroll
    for (int i = 0; i < 2; i++)
#pragma unroll
        for (int t = 0; t < 8; t++)
#pragma unroll
            for (int e = 0; e < 4; e++) o[i][t][e] = 0.0f;

    const float pre = 0.08838834764831843f * 0.02f;  // (1/sqrt(128)) / 50

    for (int kt = 0; kt <= qt; kt++) {
        const size_t krow = (size_t)(b * Tt + kt * 128);
        __syncthreads();   // prev PV readers of sKV/sP done

        {   // K tile load
            const __nv_bfloat16* gh = Khi + krow * KDIM + kvh * HD;
            const __nv_bfloat16* gl = Klo + krow * KDIM + kvh * HD;
#pragma unroll
            for (int q = 0; q < 8; q++) {
                int idx = tid + q * 256;
                int r = idx >> 4, u = idx & 15;
                uint32_t so = ((uint32_t)(u >> 3) << 14) + swz128((uint32_t)(r * 128 + (u & 7) * 16));
                cp16(sb + SK_HI + so, gh + (size_t)r * KDIM + u * 8);
                cp16(sb + SK_LO + so, gl + (size_t)r * KDIM + u * 8);
            }
            CP_COMMIT();
        }
        cp_wait<0>();
        __syncthreads();

        // ---- S = Q K^T (3-term split)
        float s[2][8][4];
#pragma unroll
        for (int i = 0; i < 2; i++)
#pragma unroll
            for (int t = 0; t < 8; t++)
#pragma unroll
                for (int e = 0; e < 4; e++) s[i][t][e] = 0.0f;

#pragma unroll
        for (int ks = 0; ks < 8; ks++) {
            uint32_t ah[2][4], al[2][4];
#pragma unroll
            for (int i = 0; i < 2; i++) {
                uint32_t c = ks * 32 + ((uint32_t)(lane >> 4) << 4);
                uint32_t row = wm * 32 + i * 16 + (lane & 15);
                uint32_t off = ((c >> 7) << 14) + swz128(row * 128 + (c & 127));
                ldsm4(ah[i], sb + SQ_HI + off);
                ldsm4(al[i], sb + SQ_LO + off);
            }
#pragma unroll
            for (int jt = 0; jt < 4; jt++) {
                uint32_t bh[4], bl[4];
                uint32_t c = ks * 32 + (((uint32_t)(lane >> 3) & 1u) << 4);
                uint32_t j = wn * 64 + jt * 16 + (lane & 7) + ((uint32_t)(lane >> 4) << 3);
                uint32_t off = ((c >> 7) << 14) + swz128(j * 128 + (c & 127));
                ldsm4(bh, sb + SK_HI + off);
                ldsm4(bl, sb + SK_LO + off);
#pragma unroll
                for (int i = 0; i < 2; i++)
#pragma unroll
                    for (int sub = 0; sub < 2; sub++) {
                        float* d = s[i][jt * 2 + sub];
                        mma16816(d, ah[i], bh + sub * 2);
                        mma16816(d, ah[i], bl + sub * 2);
                        mma16816(d, al[i], bh + sub * 2);
                    }
            }
        }

        // ---- softcap (poly tanh) + causal mask + row-max partials
        const bool diag = (kt == qt);
        float rmx[2][2] = {{-INFINITY, -INFINITY}, {-INFINITY, -INFINITY}};
#pragma unroll
        for (int i = 0; i < 2; i++)
#pragma unroll
            for (int t = 0; t < 8; t++)
#pragma unroll
                for (int e = 0; e < 4; e++) {
                    float x = s[i][t][e] * pre;
                    float x2 = x * x;
                    float th = x * (1.0f + x2 * (-0.33333333f + x2 * (0.13333333f - 0.05396825f * x2)));
                    float v = 50.0f * th;
                    if (diag) {
                        int r  = wm * 32 + i * 16 + (lane >> 2) + ((e >> 1) << 3);
                        int cc = wn * 64 + t * 8 + ((lane & 3) << 1) + (e & 1);
                        if (cc > r) v = -1e30f;
                    }
                    s[i][t][e] = v;
                    rmx[i][e >> 1] = fmaxf(rmx[i][e >> 1], v);
                }
#pragma unroll
        for (int i = 0; i < 2; i++)
#pragma unroll
            for (int h = 0; h < 2; h++) {
                float m = rmx[i][h];
                m = fmaxf(m, __shfl_xor_sync(0xffffffffu, m, 1));
                m = fmaxf(m, __shfl_xor_sync(0xffffffffu, m, 2));
                if ((lane & 3) == 0)
                    pmax[wn * 128 + wm * 32 + i * 16 + h * 8 + (lane >> 2)] = m;
            }
        __syncthreads();   // K ldsm done + pmax visible

        {   // V tile load into the K buffers (overlaps softmax)
            const __nv_bfloat16* gh = Vhi + krow * KDIM + kvh * HD;
            const __nv_bfloat16* gl = Vlo + krow * KDIM + kvh * HD;
#pragma unroll
            for (int q = 0; q < 8; q++) {
                int idx = tid + q * 256;
                int r = idx >> 4, u = idx & 15;
                uint32_t so = ((uint32_t)(u >> 3) << 14) + swz128((uint32_t)(r * 128 + (u & 7) * 16));
                cp16(sb + SK_HI + so, gh + (size_t)r * KDIM + u * 8);
                cp16(sb + SK_LO + so, gl + (size_t)r * KDIM + u * 8);
            }
            CP_COMMIT();
        }
        if (tid < 128) {
            float mo = row_m[tid];
            float mn = fmaxf(mo, fmaxf(pmax[tid], pmax[128 + tid]));
            row_m[tid] = mn;
            row_c[tid] = __expf(mo - mn);
        }
        __syncthreads();   // row_m/row_c visible

        // ---- p = exp(s - m); split to bf16 hi/lo in sP; row-sums; rescale O
        float rsum[2][2] = {{0.f, 0.f}, {0.f, 0.f}};
#pragma unroll
        for (int i = 0; i < 2; i++)
#pragma unroll
            for (int h = 0; h < 2; h++) {
                int r = wm * 32 + i * 16 + h * 8 + (lane >> 2);
                float mr = row_m[r];
                float cr = row_c[r];
#pragma unroll
                for (int t = 0; t < 8; t++) {
                    float p0 = __expf(s[i][t][h * 2 + 0] - mr);
                    float p1 = __expf(s[i][t][h * 2 + 1] - mr);
                    rsum[i][h] += p0 + p1;
                    __nv_bfloat16 h0 = __float2bfloat16(p0);
                    __nv_bfloat16 h1 = __float2bfloat16(p1);
                    uint32_t cb = (uint32_t)(t * 8 + ((lane & 3) << 1)) * 2;
                    uint32_t off = ((uint32_t)wn << 14) + swz128((uint32_t)r * 128 + cb);
                    *(__nv_bfloat162*)(smraw + SP_HI + off) = __nv_bfloat162(h0, h1);
                    *(__nv_bfloat162*)(smraw + SP_LO + off) = __nv_bfloat162(
                        __float2bfloat16(p0 - __bfloat162float(h0)),
                        __float2bfloat16(p1 - __bfloat162float(h1)));
                    o[i][t][h * 2 + 0] *= cr;
                    o[i][t][h * 2 + 1] *= cr;
                }
            }
#pragma unroll
        for (int i = 0; i < 2; i++)
#pragma unroll
            for (int h = 0; h < 2; h++) {
                float sv = rsum[i][h];
                sv += __shfl_xor_sync(0xffffffffu, sv, 1);
                sv += __shfl_xor_sync(0xffffffffu, sv, 2);
                if ((lane & 3) == 0)
                    psum[wn * 128 + wm * 32 + i * 16 + h * 8 + (lane >> 2)] = sv;
            }
        cp_wait<0>();
        __syncthreads();   // V + sP + psum visible
        if (tid < 128)
            row_l[tid] = row_l[tid] * row_c[tid] + psum[tid] + psum[128 + tid];

        // ---- O += P V (3-term split; V via ldmatrix.trans)
#pragma unroll
        for (int ks = 0; ks < 8; ks++) {
            uint32_t ph[2][4], pl[2][4];
#pragma unroll
            for (int i = 0; i < 2; i++) {
                uint32_t c = ks * 32 + ((uint32_t)(lane >> 4) << 4);
                uint32_t row = wm * 32 + i * 16 + (lane & 15);
                uint32_t off = ((c >> 7) << 14) + swz128(row * 128 + (c & 127));
                ldsm4(ph[i], sb + SP_HI + off);
                ldsm4(pl[i], sb + SP_LO + off);
            }
#pragma unroll
            for (int dt = 0; dt < 4; dt++) {
                uint32_t vh[4], vl[4];
                uint32_t dbase = wn * 64 + dt * 16 + ((uint32_t)(lane >> 4) << 3);
                uint32_t j = ks * 16 + (lane & 15);
                uint32_t off = ((dbase >> 6) << 14) + swz128(j * 128 + (dbase & 63) * 2);
                ldsm4t(vh, sb + SK_HI + off);
                ldsm4t(vl, sb + SK_LO + off);
#pragma unroll
                for (int i = 0; i < 2; i++)
#pragma unroll
                    for (int sub = 0; sub < 2; sub++) {
                        float* d = o[i][dt * 2 + sub];
                        mma16816(d, ph[i], vh + sub * 2);
                        mma16816(d, ph[i], vl + sub * 2);
                        mma16816(d, pl[i], vh + sub * 2);
                    }
            }
        }
    }

    __syncthreads();   // row_l final visible

    // ---- epilogue: normalize, write O directly as bf16 hi/lo
#pragma unroll
    for (int i = 0; i < 2; i++)
#pragma unroll
        for (int h = 0; h < 2; h++) {
            int r = wm * 32 + i * 16 + h * 8 + (lane >> 2);
            float inv = 1.0f / row_l[r];
            size_t gro = (qrow + r) * QDIM + g * HD;
#pragma unroll
            for (int t = 0; t < 8; t++) {
                int cc = wn * 64 + t * 8 + ((lane & 3) << 1);
                float v0 = o[i][t][h * 2 + 0] * inv;
                float v1 = o[i][t][h * 2 + 1] * inv;
                __nv_bfloat16 h0 = __float2bfloat16(v0);
                __nv_bfloat16 h1 = __float2bfloat16(v1);
                *(__nv_bfloat162*)(Ohi + gro + cc) = __nv_bfloat162(h0, h1);
                *(__nv_bfloat162*)(Olo + gro + cc) = __nv_bfloat162(
                    __float2bfloat16(v0 - __bfloat162float(h0)),
                    __float2bfloat16(v1 - __bfloat162float(h1)));
            }
        }
}

// ---------------------------------------------------------------------------
extern "C" void kernel_launch(void* const* d_in, const int* in_sizes, int n_in,
                              void* d_out, int out_size)
{
    const float* x  = (const float*)d_in[0];
    const float* wq = (const float*)d_in[2];
    const float* wk = (const float*)d_in[3];
    const float* wv = (const float*)d_in[4];
    const float* wo = (const float*)d_in[5];
    float* out = (float*)d_out;

    float *Qp, *Kp, *Vp;
    cudaGetSymbolAddress((void**)&Qp, g_Q);
    cudaGetSymbolAddress((void**)&Kp, g_K);
    cudaGetSymbolAddress((void**)&Vp, g_V);
    __nv_bfloat16 *xhi, *xlo, *khi, *klo, *vhi, *vlo, *ohi, *olo;
    __nv_bfloat16 *wqh, *wql, *wkh, *wkl, *wvh, *wvl, *woh, *wol;
    cudaGetSymbolAddress((void**)&xhi, g_xhi);
    cudaGetSymbolAddress((void**)&xlo, g_xlo);
    cudaGetSymbolAddress((void**)&khi, g_Khi);
    cudaGetSymbolAddress((void**)&klo, g_Klo);
    cudaGetSymbolAddress((void**)&vhi, g_Vhi);
    cudaGetSymbolAddress((void**)&vlo, g_Vlo);
    cudaGetSymbolAddress((void**)&ohi, g_Ohi);
    cudaGetSymbolAddress((void**)&olo, g_Olo);
    cudaGetSymbolAddress((void**)&wqh, g_wqT_hi);
    cudaGetSymbolAddress((void**)&wql, g_wqT_lo);
    cudaGetSymbolAddress((void**)&wkh, g_wkT_hi);
    cudaGetSymbolAddress((void**)&wkl, g_wkT_lo);
    cudaGetSymbolAddress((void**)&wvh, g_wvT_hi);
    cudaGetSymbolAddress((void**)&wvl, g_wvT_lo);
    cudaGetSymbolAddress((void**)&woh, g_woT_hi);
    cudaGetSymbolAddress((void**)&wol, g_woT_lo);

    // ---- prep
    {
        int n4 = MROWS * Cc / 4;
        split_bf16<<<(n4 + 255) / 256, 256>>>(x, xhi, xlo, n4);
    }
    transpose_split<<<dim3(QDIM / 32, Cc / 32), dim3(32, 8)>>>(wq, wqh, wql, Cc, QDIM);
    transpose_split<<<dim3(KDIM / 32, Cc / 32), dim3(32, 8)>>>(wk, wkh, wkl, Cc, KDIM);
    transpose_split<<<dim3(KDIM / 32, Cc / 32), dim3(32, 8)>>>(wv, wvh, wvl, Cc, KDIM);
    transpose_split<<<dim3(Cc / 32, QDIM / 32), dim3(32, 8)>>>(wo, woh, wol, QDIM, Cc);
    rope_table_kernel<<<(Tt * 64 + 255) / 256, 256>>>();

    // ---- projections (HMMA)
    cudaFuncSetAttribute(gemm_hmma, cudaFuncAttributeMaxDynamicSharedMemorySize, GSMEM);
    gemm_hmma<<<dim3(QDIM / 128, MROWS / 128), 256, GSMEM>>>(xhi, xlo, wqh, wql, Qp, QDIM, Cc);
    gemm_hmma<<<dim3(KDIM / 128, MROWS / 128), 256, GSMEM>>>(xhi, xlo, wkh, wkl, Kp, KDIM, Cc);
    gemm_hmma<<<dim3(KDIM / 128, MROWS / 128), 256, GSMEM>>>(xhi, xlo, wvh, wvl, Vp, KDIM, Cc);

    // ---- rope + split Q/K (Q reuses x split buffers), split V
    {
        const int pairs = MROWS * (NH + NKV) * 64;
        rope_split<<<(pairs + 255) / 256, 256>>>(Qp, Kp, xhi, xlo, khi, klo);
        int n4 = MROWS * KDIM / 4;
        split_bf16<<<(n4 + 255) / 256, 256>>>(Vp, vhi, vlo, n4);
    }

    // ---- attention (HMMA)
    cudaFuncSetAttribute(attn_hmma, cudaFuncAttributeMaxDynamicSharedMemorySize, ATT_SMEM);
    attn_hmma<<<dim3(Tt / 128, NH, Bb), 256, ATT_SMEM>>>(xhi, xlo, khi, klo, vhi, vlo, ohi, olo);

    // ---- output projection (HMMA)
    gemm_hmma<<<dim3(QDIM / 128, MROWS / 128), 256, GSMEM>>>(ohi, olo, woh, wol, out, QDIM, Cc);
}

// round 5
// speedup vs baseline: 5.0969x; 1.2200x over previous
#include <cuda_runtime.h>
#include <cuda_bf16.h>
#include <cuda_fp16.h>
#include <math.h>
#include <stdint.h>

#define Bb   2
#define Tt   2048
#define Cc   2048
#define NH   16
#define NKV  4
#define HD   128
#define QDIM (NH * HD)    // 2048
#define KDIM (NKV * HD)   // 512
#define NALL (QDIM + 2 * KDIM)   // 3072 fused projection width
#define MROWS (Bb * Tt)   // 4096

// ------------------------- device scratch (no allocs allowed) --------------
__device__ float g_QKV[(size_t)MROWS * NALL];      // fused projection output (fp32)
__device__ float2 g_rope[Tt * 64];

__device__ __half g_Qh[(size_t)MROWS * QDIM];      // rope'd fp16
__device__ __half g_Kh[(size_t)MROWS * KDIM];
__device__ __half g_Vh[(size_t)MROWS * KDIM];

__device__ __nv_bfloat16 g_xhi[(size_t)MROWS * Cc];
__device__ __nv_bfloat16 g_xlo[(size_t)MROWS * Cc];
__device__ __nv_bfloat16 g_Ohi[(size_t)MROWS * QDIM];
__device__ __nv_bfloat16 g_Olo[(size_t)MROWS * QDIM];
__device__ __nv_bfloat16 g_wAll_hi[(size_t)NALL * Cc];   // packed wq^T | wk^T | wv^T
__device__ __nv_bfloat16 g_wAll_lo[(size_t)NALL * Cc];
__device__ __nv_bfloat16 g_woT_hi[(size_t)Cc * QDIM];
__device__ __nv_bfloat16 g_woT_lo[(size_t)Cc * QDIM];

// ------------------------- PTX helpers (sm_80-era, base-target-safe) -------
__device__ __forceinline__ uint32_t smem_u32(const void* p) {
    uint32_t a;
    asm("{ .reg .u64 t; cvta.to.shared.u64 t, %1; cvt.u32.u64 %0, t; }" : "=r"(a) : "l"(p));
    return a;
}
__device__ __forceinline__ void cp16(uint32_t saddr, const void* g) {
    asm volatile("cp.async.cg.shared.global [%0], [%1], 16;" :: "r"(saddr), "l"(g));
}
#define CP_COMMIT() asm volatile("cp.async.commit_group;" ::: "memory")
template <int N> __device__ __forceinline__ void cp_wait() {
    asm volatile("cp.async.wait_group %0;" :: "n"(N) : "memory");
}
__device__ __forceinline__ void ldsm4(uint32_t* r, uint32_t addr) {
    asm volatile("ldmatrix.sync.aligned.m8n8.x4.shared.b16 {%0,%1,%2,%3}, [%4];"
                 : "=r"(r[0]), "=r"(r[1]), "=r"(r[2]), "=r"(r[3]) : "r"(addr));
}
__device__ __forceinline__ void ldsm4t(uint32_t* r, uint32_t addr) {
    asm volatile("ldmatrix.sync.aligned.m8n8.x4.trans.shared.b16 {%0,%1,%2,%3}, [%4];"
                 : "=r"(r[0]), "=r"(r[1]), "=r"(r[2]), "=r"(r[3]) : "r"(addr));
}
__device__ __forceinline__ void mma16816(float* d, const uint32_t* a, const uint32_t* b) {
    asm volatile("mma.sync.aligned.m16n8k16.row.col.f32.bf16.bf16.f32 "
                 "{%0,%1,%2,%3}, {%4,%5,%6,%7}, {%8,%9}, {%0,%1,%2,%3};"
                 : "+f"(d[0]), "+f"(d[1]), "+f"(d[2]), "+f"(d[3])
                 : "r"(a[0]), "r"(a[1]), "r"(a[2]), "r"(a[3]), "r"(b[0]), "r"(b[1]));
}
__device__ __forceinline__ void mma16816h(float* d, const uint32_t* a, const uint32_t* b) {
    asm volatile("mma.sync.aligned.m16n8k16.row.col.f32.f16.f16.f32 "
                 "{%0,%1,%2,%3}, {%4,%5,%6,%7}, {%8,%9}, {%0,%1,%2,%3};"
                 : "+f"(d[0]), "+f"(d[1]), "+f"(d[2]), "+f"(d[3])
                 : "r"(a[0]), "r"(a[1]), "r"(a[2]), "r"(a[3]), "r"(b[0]), "r"(b[1]));
}
__device__ __forceinline__ uint32_t swz128(uint32_t o) { return o ^ ((o >> 3) & 0x70); }

// ------------------------- prep kernels ------------------------------------
__global__ void split_bf16(const float* __restrict__ src,
                           __nv_bfloat16* __restrict__ hi,
                           __nv_bfloat16* __restrict__ lo, int n4) {
    int i = blockIdx.x * blockDim.x + threadIdx.x;
    if (i >= n4) return;
    float4 v = ((const float4*)src)[i];
    __nv_bfloat16 h0 = __float2bfloat16(v.x), h1 = __float2bfloat16(v.y);
    __nv_bfloat16 h2 = __float2bfloat16(v.z), h3 = __float2bfloat16(v.w);
    __nv_bfloat162* hp = (__nv_bfloat162*)hi;
    __nv_bfloat162* lp = (__nv_bfloat162*)lo;
    hp[i * 2]     = __nv_bfloat162(h0, h1);
    hp[i * 2 + 1] = __nv_bfloat162(h2, h3);
    lp[i * 2]     = __nv_bfloat162(__float2bfloat16(v.x - __bfloat162float(h0)),
                                   __float2bfloat16(v.y - __bfloat162float(h1)));
    lp[i * 2 + 1] = __nv_bfloat162(__float2bfloat16(v.z - __bfloat162float(h2)),
                                   __float2bfloat16(v.w - __bfloat162float(h3)));
}

// all 4 weight transposes in one launch; z selects matrix.
__global__ void transpose_split_all(const float* __restrict__ wq, const float* __restrict__ wk,
                                    const float* __restrict__ wv, const float* __restrict__ wo,
                                    __nv_bfloat16* __restrict__ wallh, __nv_bfloat16* __restrict__ walll,
                                    __nv_bfloat16* __restrict__ woh, __nv_bfloat16* __restrict__ wol)
{
    __shared__ float t[32][33];
    const int z = blockIdx.z;
    const float* src; __nv_bfloat16 *hi, *lo; int N, rowoff;
    if (z == 0)      { src = wq; N = QDIM; rowoff = 0;    hi = wallh; lo = walll; }
    else if (z == 1) { src = wk; N = KDIM; rowoff = 2048; hi = wallh; lo = walll; }
    else if (z == 2) { src = wv; N = KDIM; rowoff = 2560; hi = wallh; lo = walll; }
    else             { src = wo; N = QDIM; rowoff = 0;    hi = woh;   lo = wol;   }
    const int n0 = blockIdx.x * 32;
    if (n0 >= N) return;
    const int k0 = blockIdx.y * 32;
    const int tx = threadIdx.x, ty = threadIdx.y;  // 32x8
#pragma unroll
    for (int i = 0; i < 4; i++)
        t[ty + 8 * i][tx] = src[(size_t)(k0 + ty + 8 * i) * N + n0 + tx];
    __syncthreads();
#pragma unroll
    for (int i = 0; i < 4; i++) {
        float v = t[tx][ty + 8 * i];
        __nv_bfloat16 h = __float2bfloat16(v);
        size_t o = (size_t)(rowoff + n0 + ty + 8 * i) * Cc + k0 + tx;
        hi[o] = h;
        lo[o] = __float2bfloat16(v - __bfloat162float(h));
    }
}

// ------------------------- HMMA split-precision GEMM (bf16 3-term) ----------
#define GSMEM (2 * 65536 + 128)
__global__ __launch_bounds__(256) void gemm_hmma(
    const __nv_bfloat16* __restrict__ Ahi, const __nv_bfloat16* __restrict__ Alo,
    const __nv_bfloat16* __restrict__ Bhi, const __nv_bfloat16* __restrict__ Blo,
    float* __restrict__ C, int Cstride, int Kdim)
{
    extern __shared__ char smraw[];
    const uint32_t sb = (smem_u32(smraw) + 127) & ~127u;
    const int tid = threadIdx.x;
    const int lane = tid & 31, wid = tid >> 5;
    const int wm = wid >> 1, wn = wid & 1;
    const int bm = blockIdx.y * 128, bn = blockIdx.x * 128;

    float acc[2][8][4];
#pragma unroll
    for (int i = 0; i < 2; i++)
#pragma unroll
        for (int t = 0; t < 8; t++)
#pragma unroll
            for (int e = 0; e < 4; e++) acc[i][t][e] = 0.0f;

    const int nch = Kdim >> 6;

    auto prefetch = [&](int ch) {
        const uint32_t st = sb + (ch & 1) * 65536;
        const int kc = ch << 6;
#pragma unroll
        for (int q = 0; q < 4; q++) {
            int idx = tid + q * 256;
            int r = idx >> 3, u = idx & 7;
            uint32_t so = swz128((uint32_t)(r * 128 + u * 16));
            const size_t ga = (size_t)(bm + r) * Kdim + kc + u * 8;
            const size_t gb = (size_t)(bn + r) * Kdim + kc + u * 8;
            cp16(st + so,         Ahi + ga);
            cp16(st + 16384 + so, Alo + ga);
            cp16(st + 32768 + so, Bhi + gb);
            cp16(st + 49152 + so, Blo + gb);
        }
        CP_COMMIT();
    };

    prefetch(0);
    const uint32_t arow = wm * 32 + (lane & 15);
    const uint32_t acb  = ((uint32_t)(lane >> 4)) << 4;
    const uint32_t brow = wn * 64 + (lane & 7) + (((uint32_t)(lane >> 4)) << 3);
    const uint32_t bcb  = (((uint32_t)(lane >> 3)) & 1u) << 4;

    for (int ch = 0; ch < nch; ch++) {
        if (ch + 1 < nch) { prefetch(ch + 1); cp_wait<1>(); }
        else              { cp_wait<0>(); }
        __syncthreads();
        const uint32_t st = sb + (ch & 1) * 65536;
#pragma unroll
        for (int s = 0; s < 4; s++) {
            const uint32_t kb = s * 32;
            uint32_t ah[2][4], al[2][4], bh[4][4], bl[4][4];
#pragma unroll
            for (int i = 0; i < 2; i++) {
                uint32_t off = swz128((arow + i * 16) * 128 + kb + acb);
                ldsm4(ah[i], st + off);
                ldsm4(al[i], st + 16384 + off);
            }
#pragma unroll
            for (int j = 0; j < 4; j++) {
                uint32_t off = swz128((brow + j * 16) * 128 + kb + bcb);
                ldsm4(bh[j], st + 32768 + off);
                ldsm4(bl[j], st + 49152 + off);
            }
#pragma unroll
            for (int i = 0; i < 2; i++)
#pragma unroll
                for (int t = 0; t < 8; t++) {
                    const uint32_t* bhp = &bh[t >> 1][(t & 1) * 2];
                    const uint32_t* blp = &bl[t >> 1][(t & 1) * 2];
                    mma16816(acc[i][t], ah[i], bhp);
                    mma16816(acc[i][t], ah[i], blp);
                    mma16816(acc[i][t], al[i], bhp);
                }
        }
        __syncthreads();
    }

#pragma unroll
    for (int i = 0; i < 2; i++) {
        const int r0 = bm + wm * 32 + i * 16 + (lane >> 2);
#pragma unroll
        for (int t = 0; t < 8; t++) {
            const int c = bn + wn * 64 + t * 8 + (lane & 3) * 2;
            *(float2*)(C + (size_t)r0 * Cstride + c) = make_float2(acc[i][t][0], acc[i][t][1]);
            *(float2*)(C + (size_t)(r0 + 8) * Cstride + c) = make_float2(acc[i][t][2], acc[i][t][3]);
        }
    }
}

// ------------------------- RoPE table + fused rope/convert -----------------
__global__ void rope_table_kernel() {
    const int i = blockIdx.x * blockDim.x + threadIdx.x;
    if (i >= Tt * 64) return;
    const int t = i >> 6, f = i & 63;
    double inv = exp(-(double)f * 0.14391156831212787);  // ln(10000)/64
    double a = (double)t * inv;
    g_rope[i] = make_float2((float)sin(a), (float)cos(a));
}

// reads fused QKV fp32, applies rope to q/k, converts all to fp16
__global__ void rope_convert_f16(const float* __restrict__ QKV,
                                 __half* __restrict__ Qh, __half* __restrict__ Kh,
                                 __half* __restrict__ Vh)
{
    const int idx = blockIdx.x * blockDim.x + threadIdx.x;
    const int nq = MROWS * NH * 64;
    const int nk = MROWS * NKV * 64;
    const int nv = nk;
    if (idx >= nq + nk + nv) return;

    if (idx < nq + nk) {
        int f, t, srccol; size_t dbase; __half* dst;
        int bt;
        if (idx < nq) {
            f = idx & 63;
            int h = (idx >> 6) & (NH - 1);
            bt = idx >> 10;
            srccol = h * HD + f;
            dbase = (size_t)bt * QDIM + h * HD;
            dst = Qh;
        } else {
            int k = idx - nq;
            f = k & 63;
            int h = (k >> 6) & (NKV - 1);
            bt = k >> 8;
            srccol = 2048 + h * HD + f;
            dbase = (size_t)bt * KDIM + h * HD;
            dst = Kh;
        }
        t = bt & (Tt - 1);
        const float2 sc = g_rope[t * 64 + f];
        const float x1 = QKV[(size_t)bt * NALL + srccol];
        const float x2 = QKV[(size_t)bt * NALL + srccol + 64];
        dst[dbase + f]      = __float2half_rn(x1 * sc.y - x2 * sc.x);
        dst[dbase + f + 64] = __float2half_rn(x2 * sc.y + x1 * sc.x);
    } else {
        int j = idx - nq - nk;
        int f = j & 63;
        int h = (j >> 6) & (NKV - 1);
        int bt = j >> 8;
        const size_t s = (size_t)bt * NALL + 2560 + h * HD + f;
        const size_t d = (size_t)bt * KDIM + h * HD + f;
        Vh[d]      = __float2half_rn(QKV[s]);
        Vh[d + 64] = __float2half_rn(QKV[s + 64]);
    }
}

// ------------------------- fp16 HMMA flash attention -----------------------
// smem byte layout
#define SQ  0
#define SK  32768
#define SV  65536
#define SP  98304
#define SRED 131072
#define ATT_SMEM (SRED + 896 * 4)

__global__ __launch_bounds__(256) void attn_hmma(
    const __half* __restrict__ Qh, const __half* __restrict__ Kh,
    const __half* __restrict__ Vh,
    __nv_bfloat16* __restrict__ Ohi, __nv_bfloat16* __restrict__ Olo)
{
    extern __shared__ char smraw[];
    const uint32_t sb = smem_u32(smraw);
    float* row_m = (float*)(smraw + SRED);
    float* row_l = row_m + 128;
    float* row_c = row_l + 128;
    float* pmax  = row_c + 128;   // [2][128]
    float* psum  = pmax + 256;    // [2][128]

    const int tid = threadIdx.x, lane = tid & 31, wid = tid >> 5;
    const int wm = wid >> 1, wn = wid & 1;
    const int qt = (int)gridDim.x - 1 - (int)blockIdx.x;   // heavy tiles first
    const int g = blockIdx.y, b = blockIdx.z;
    const int kvh = g & (NKV - 1);
    const int q0 = qt * 128;
    const size_t qrow = (size_t)(b * Tt + q0);

    // tile loaders (each = one cp.async group)
    auto loadQ = [&]() {
        const __half* gq = Qh + qrow * QDIM + g * HD;
#pragma unroll
        for (int q = 0; q < 8; q++) {
            int idx = tid + q * 256;
            int r = idx >> 4, u = idx & 15;
            uint32_t so = ((uint32_t)(u >> 3) << 14) + swz128((uint32_t)(r * 128 + (u & 7) * 16));
            cp16(sb + SQ + so, gq + (size_t)r * QDIM + u * 8);
        }
        CP_COMMIT();
    };
    auto loadK = [&](int kt) {
        const __half* gk = Kh + (size_t)(b * Tt + kt * 128) * KDIM + kvh * HD;
#pragma unroll
        for (int q = 0; q < 8; q++) {
            int idx = tid + q * 256;
            int r = idx >> 4, u = idx & 15;
            uint32_t so = ((uint32_t)(u >> 3) << 14) + swz128((uint32_t)(r * 128 + (u & 7) * 16));
            cp16(sb + SK + so, gk + (size_t)r * KDIM + u * 8);
        }
        CP_COMMIT();
    };
    auto loadV = [&](int kt) {
        const __half* gv = Vh + (size_t)(b * Tt + kt * 128) * KDIM + kvh * HD;
#pragma unroll
        for (int q = 0; q < 8; q++) {
            int idx = tid + q * 256;
            int r = idx >> 4, u = idx & 15;
            uint32_t so = ((uint32_t)(u >> 3) << 14) + swz128((uint32_t)(r * 128 + (u & 7) * 16));
            cp16(sb + SV + so, gv + (size_t)r * KDIM + u * 8);
        }
        CP_COMMIT();
    };

    loadQ();
    loadK(0);
    if (tid < 128) { row_m[tid] = -INFINITY; row_l[tid] = 0.0f; }

    float o[2][8][4];
#pragma unroll
    for (int i = 0; i < 2; i++)
#pragma unroll
        for (int t = 0; t < 8; t++)
#pragma unroll
            for (int e = 0; e < 4; e++) o[i][t][e] = 0.0f;

    const float pre = 0.08838834764831843f * 0.02f;  // (1/sqrt(128)) / 50

    for (int kt = 0; kt <= qt; kt++) {
        __syncthreads();                 // (a) prev PV readers of sV/sP done
        loadV(kt);
        cp_wait<1>();                    // Q + K(kt) arrived (V may be pending)
        __syncthreads();                 // (b)

        // ---- S = Q K^T (single fp16 term)
        float s[2][8][4];
#pragma unroll
        for (int i = 0; i < 2; i++)
#pragma unroll
            for (int t = 0; t < 8; t++)
#pragma unroll
                for (int e = 0; e < 4; e++) s[i][t][e] = 0.0f;

#pragma unroll
        for (int ks = 0; ks < 8; ks++) {
            uint32_t ah[2][4];
#pragma unroll
            for (int i = 0; i < 2; i++) {
                uint32_t c = ks * 32 + ((uint32_t)(lane >> 4) << 4);
                uint32_t row = wm * 32 + i * 16 + (lane & 15);
                uint32_t off = ((c >> 7) << 14) + swz128(row * 128 + (c & 127));
                ldsm4(ah[i], sb + SQ + off);
            }
#pragma unroll
            for (int jt = 0; jt < 4; jt++) {
                uint32_t bh[4];
                uint32_t c = ks * 32 + (((uint32_t)(lane >> 3) & 1u) << 4);
                uint32_t j = wn * 64 + jt * 16 + (lane & 7) + ((uint32_t)(lane >> 4) << 3);
                uint32_t off = ((c >> 7) << 14) + swz128(j * 128 + (c & 127));
                ldsm4(bh, sb + SK + off);
#pragma unroll
                for (int i = 0; i < 2; i++)
#pragma unroll
                    for (int sub = 0; sub < 2; sub++)
                        mma16816h(s[i][jt * 2 + sub], ah[i], bh + sub * 2);
            }
        }

        // ---- softcap (poly tanh) + causal mask + row-max partials
        const bool diag = (kt == qt);
        float rmx[2][2] = {{-INFINITY, -INFINITY}, {-INFINITY, -INFINITY}};
#pragma unroll
        for (int i = 0; i < 2; i++)
#pragma unroll
            for (int t = 0; t < 8; t++)
#pragma unroll
                for (int e = 0; e < 4; e++) {
                    float x = s[i][t][e] * pre;
                    float x2 = x * x;
                    float th = x * (1.0f + x2 * (-0.33333333f + x2 * (0.13333333f - 0.05396825f * x2)));
                    float v = 50.0f * th;
                    if (diag) {
                        int r  = wm * 32 + i * 16 + (lane >> 2) + ((e >> 1) << 3);
                        int cc = wn * 64 + t * 8 + ((lane & 3) << 1) + (e & 1);
                        if (cc > r) v = -1e30f;
                    }
                    s[i][t][e] = v;
                    rmx[i][e >> 1] = fmaxf(rmx[i][e >> 1], v);
                }
#pragma unroll
        for (int i = 0; i < 2; i++)
#pragma unroll
            for (int h = 0; h < 2; h++) {
                float m = rmx[i][h];
                m = fmaxf(m, __shfl_xor_sync(0xffffffffu, m, 1));
                m = fmaxf(m, __shfl_xor_sync(0xffffffffu, m, 2));
                if ((lane & 3) == 0)
                    pmax[wn * 128 + wm * 32 + i * 16 + h * 8 + (lane >> 2)] = m;
            }
        __syncthreads();                 // (c) sK consumed; pmax visible

        if (kt < qt) loadK(kt + 1);      // prefetch next K into sK

        if (tid < 128) {
            float mo = row_m[tid];
            float mn = fmaxf(mo, fmaxf(pmax[tid], pmax[128 + tid]));
            row_m[tid] = mn;
            row_c[tid] = __expf(mo - mn);
        }
        __syncthreads();                 // (d) row_m/row_c visible

        // ---- p = exp(s - m) -> fp16 sP; row-sums; rescale O
        float rsum[2][2] = {{0.f, 0.f}, {0.f, 0.f}};
#pragma unroll
        for (int i = 0; i < 2; i++)
#pragma unroll
            for (int h = 0; h < 2; h++) {
                int r = wm * 32 + i * 16 + h * 8 + (lane >> 2);
                float mr = row_m[r];
                float cr = row_c[r];
#pragma unroll
                for (int t = 0; t < 8; t++) {
                    float p0 = __expf(s[i][t][h * 2 + 0] - mr);
                    float p1 = __expf(s[i][t][h * 2 + 1] - mr);
                    rsum[i][h] += p0 + p1;
                    uint32_t cb = (uint32_t)(t * 8 + ((lane & 3) << 1)) * 2;
                    uint32_t off = ((uint32_t)wn << 14) + swz128((uint32_t)r * 128 + cb);
                    *(__half2*)(smraw + SP + off) = __floats2half2_rn(p0, p1);
                    o[i][t][h * 2 + 0] *= cr;
                    o[i][t][h * 2 + 1] *= cr;
                }
            }
#pragma unroll
        for (int i = 0; i < 2; i++)
#pragma unroll
            for (int h = 0; h < 2; h++) {
                float sv = rsum[i][h];
                sv += __shfl_xor_sync(0xffffffffu, sv, 1);
                sv += __shfl_xor_sync(0xffffffffu, sv, 2);
                if ((lane & 3) == 0)
                    psum[wn * 128 + wm * 32 + i * 16 + h * 8 + (lane >> 2)] = sv;
            }
        if (kt < qt) cp_wait<1>();       // V(kt) done (K(kt+1) may be pending)
        else         cp_wait<0>();
        __syncthreads();                 // (e) sV + sP + psum visible
        if (tid < 128)
            row_l[tid] = row_l[tid] * row_c[tid] + psum[tid] + psum[128 + tid];

        // ---- O += P V (single fp16 term; V via ldmatrix.trans)
#pragma unroll
        for (int ks = 0; ks < 8; ks++) {
            uint32_t ph[2][4];
#pragma unroll
            for (int i = 0; i < 2; i++) {
                uint32_t c = ks * 32 + ((uint32_t)(lane >> 4) << 4);
                uint32_t row = wm * 32 + i * 16 + (lane & 15);
                uint32_t off = ((c >> 7) << 14) + swz128(row * 128 + (c & 127));
                ldsm4(ph[i], sb + SP + off);
            }
#pragma unroll
            for (int dt = 0; dt < 4; dt++) {
                uint32_t vh[4];
                uint32_t dbase = wn * 64 + dt * 16 + ((uint32_t)(lane >> 4) << 3);
                uint32_t j = ks * 16 + (lane & 15);
                uint32_t off = ((dbase >> 6) << 14) + swz128(j * 128 + (dbase & 63) * 2);
                ldsm4t(vh, sb + SV + off);
#pragma unroll
                for (int i = 0; i < 2; i++)
#pragma unroll
                    for (int sub = 0; sub < 2; sub++)
                        mma16816h(o[i][dt * 2 + sub], ph[i], vh + sub * 2);
            }
        }
    }

    __syncthreads();   // row_l final visible

    // ---- epilogue: normalize, write O as bf16 hi/lo (for 3-term out GEMM)
#pragma unroll
    for (int i = 0; i < 2; i++)
#pragma unroll
        for (int h = 0; h < 2; h++) {
            int r = wm * 32 + i * 16 + h * 8 + (lane >> 2);
            float inv = 1.0f / row_l[r];
            size_t gro = (qrow + r) * QDIM + g * HD;
#pragma unroll
            for (int t = 0; t < 8; t++) {
                int cc = wn * 64 + t * 8 + ((lane & 3) << 1);
                float v0 = o[i][t][h * 2 + 0] * inv;
                float v1 = o[i][t][h * 2 + 1] * inv;
                __nv_bfloat16 h0 = __float2bfloat16(v0);
                __nv_bfloat16 h1 = __float2bfloat16(v1);
                *(__nv_bfloat162*)(Ohi + gro + cc) = __nv_bfloat162(h0, h1);
                *(__nv_bfloat162*)(Olo + gro + cc) = __nv_bfloat162(
                    __float2bfloat16(v0 - __bfloat162float(h0)),
                    __float2bfloat16(v1 - __bfloat162float(h1)));
            }
        }
}

// ---------------------------------------------------------------------------
extern "C" void kernel_launch(void* const* d_in, const int* in_sizes, int n_in,
                              void* d_out, int out_size)
{
    const float* x  = (const float*)d_in[0];
    const float* wq = (const float*)d_in[2];
    const float* wk = (const float*)d_in[3];
    const float* wv = (const float*)d_in[4];
    const float* wo = (const float*)d_in[5];
    float* out = (float*)d_out;

    float* qkv;
    cudaGetSymbolAddress((void**)&qkv, g_QKV);
    __half *qh, *kh, *vh;
    cudaGetSymbolAddress((void**)&qh, g_Qh);
    cudaGetSymbolAddress((void**)&kh, g_Kh);
    cudaGetSymbolAddress((void**)&vh, g_Vh);
    __nv_bfloat16 *xhi, *xlo, *ohi, *olo, *wah, *wal, *woh, *wol;
    cudaGetSymbolAddress((void**)&xhi, g_xhi);
    cudaGetSymbolAddress((void**)&xlo, g_xlo);
    cudaGetSymbolAddress((void**)&ohi, g_Ohi);
    cudaGetSymbolAddress((void**)&olo, g_Olo);
    cudaGetSymbolAddress((void**)&wah, g_wAll_hi);
    cudaGetSymbolAddress((void**)&wal, g_wAll_lo);
    cudaGetSymbolAddress((void**)&woh, g_woT_hi);
    cudaGetSymbolAddress((void**)&wol, g_woT_lo);

    // ---- prep
    {
        int n4 = MROWS * Cc / 4;
        split_bf16<<<(n4 + 255) / 256, 256>>>(x, xhi, xlo, n4);
    }
    transpose_split_all<<<dim3(QDIM / 32, Cc / 32, 4), dim3(32, 8)>>>(
        wq, wk, wv, wo, wah, wal, woh, wol);
    rope_table_kernel<<<(Tt * 64 + 255) / 256, 256>>>();

    // ---- fused QKV projection (bf16 3-term HMMA)
    cudaFuncSetAttribute(gemm_hmma, cudaFuncAttributeMaxDynamicSharedMemorySize, GSMEM);
    gemm_hmma<<<dim3(NALL / 128, MROWS / 128), 256, GSMEM>>>(
        xhi, xlo, wah, wal, qkv, NALL, Cc);

    // ---- rope + fp16 convert
    {
        const int total = MROWS * (NH + NKV + NKV) * 64;
        rope_convert_f16<<<(total + 255) / 256, 256>>>(qkv, qh, kh, vh);
    }

    // ---- attention (fp16 single-term HMMA)
    cudaFuncSetAttribute(attn_hmma, cudaFuncAttributeMaxDynamicSharedMemorySize, ATT_SMEM);
    attn_hmma<<<dim3(Tt / 128, NH, Bb), 256, ATT_SMEM>>>(qh, kh, vh, ohi, olo);

    // ---- output projection (bf16 3-term HMMA)
    gemm_hmma<<<dim3(QDIM / 128, MROWS / 128), 256, GSMEM>>>(
        ohi, olo, woh, wol, out, QDIM, Cc);
}

// round 6
// speedup vs baseline: 10.0233x; 1.9666x over previous
#include <cuda_runtime.h>
#include <cuda_bf16.h>
#include <cuda_fp16.h>
#include <math.h>
#include <stdint.h>

#define Bb   2
#define Tt   2048
#define Cc   2048
#define NH   16
#define NKV  4
#define HD   128
#define QDIM (NH * HD)    // 2048
#define KDIM (NKV * HD)   // 512
#define NALL (QDIM + 2 * KDIM)   // 3072 fused projection width
#define MROWS (Bb * Tt)   // 4096

// ------------------------- device scratch (no allocs allowed) --------------
__device__ float2 g_rope[Tt * 64];
__device__ __half g_xh[(size_t)MROWS * Cc];
__device__ __half g_QKVh[(size_t)MROWS * NALL];
__device__ __half g_Oh[(size_t)MROWS * QDIM];
__device__ __half g_wAllT[(size_t)NALL * Cc];   // packed wq^T | wk^T | wv^T (fp16, K-contig)
__device__ __half g_woT[(size_t)Cc * QDIM];

// ------------------------- PTX helpers (sm_80-era, base-target-safe) -------
__device__ __forceinline__ uint32_t smem_u32(const void* p) {
    uint32_t a;
    asm("{ .reg .u64 t; cvta.to.shared.u64 t, %1; cvt.u32.u64 %0, t; }" : "=r"(a) : "l"(p));
    return a;
}
__device__ __forceinline__ void cp16(uint32_t saddr, const void* g) {
    asm volatile("cp.async.cg.shared.global [%0], [%1], 16;" :: "r"(saddr), "l"(g));
}
#define CP_COMMIT() asm volatile("cp.async.commit_group;" ::: "memory")
template <int N> __device__ __forceinline__ void cp_wait() {
    asm volatile("cp.async.wait_group %0;" :: "n"(N) : "memory");
}
__device__ __forceinline__ void ldsm4(uint32_t* r, uint32_t addr) {
    asm volatile("ldmatrix.sync.aligned.m8n8.x4.shared.b16 {%0,%1,%2,%3}, [%4];"
                 : "=r"(r[0]), "=r"(r[1]), "=r"(r[2]), "=r"(r[3]) : "r"(addr));
}
__device__ __forceinline__ void ldsm4t(uint32_t* r, uint32_t addr) {
    asm volatile("ldmatrix.sync.aligned.m8n8.x4.trans.shared.b16 {%0,%1,%2,%3}, [%4];"
                 : "=r"(r[0]), "=r"(r[1]), "=r"(r[2]), "=r"(r[3]) : "r"(addr));
}
__device__ __forceinline__ void mma16816h(float* d, const uint32_t* a, const uint32_t* b) {
    asm volatile("mma.sync.aligned.m16n8k16.row.col.f32.f16.f16.f32 "
                 "{%0,%1,%2,%3}, {%4,%5,%6,%7}, {%8,%9}, {%0,%1,%2,%3};"
                 : "+f"(d[0]), "+f"(d[1]), "+f"(d[2]), "+f"(d[3])
                 : "r"(a[0]), "r"(a[1]), "r"(a[2]), "r"(a[3]), "r"(b[0]), "r"(b[1]));
}
__device__ __forceinline__ uint32_t swz128(uint32_t o) { return o ^ ((o >> 3) & 0x70); }

// ------------------------- prep kernels ------------------------------------
__global__ void to_f16(const float* __restrict__ src, __half* __restrict__ dst, int n4) {
    int i = blockIdx.x * blockDim.x + threadIdx.x;
    if (i >= n4) return;
    float4 v = ((const float4*)src)[i];
    __half2* d = (__half2*)dst;
    d[i * 2]     = __floats2half2_rn(v.x, v.y);
    d[i * 2 + 1] = __floats2half2_rn(v.z, v.w);
}

// all 4 weight transposes in one launch; z selects matrix. fp32 [K,N] -> fp16 [N,K]
__global__ void transpose_f16_all(const float* __restrict__ wq, const float* __restrict__ wk,
                                  const float* __restrict__ wv, const float* __restrict__ wo,
                                  __half* __restrict__ wallT, __half* __restrict__ woT)
{
    __shared__ float t[32][33];
    const int z = blockIdx.z;
    const float* src; __half* dst; int N, rowoff;
    if (z == 0)      { src = wq; N = QDIM; rowoff = 0;    dst = wallT; }
    else if (z == 1) { src = wk; N = KDIM; rowoff = 2048; dst = wallT; }
    else if (z == 2) { src = wv; N = KDIM; rowoff = 2560; dst = wallT; }
    else             { src = wo; N = QDIM; rowoff = 0;    dst = woT;   }
    const int n0 = blockIdx.x * 32;
    if (n0 >= N) return;
    const int k0 = blockIdx.y * 32;
    const int tx = threadIdx.x, ty = threadIdx.y;  // 32x8
#pragma unroll
    for (int i = 0; i < 4; i++)
        t[ty + 8 * i][tx] = src[(size_t)(k0 + ty + 8 * i) * N + n0 + tx];
    __syncthreads();
#pragma unroll
    for (int i = 0; i < 4; i++)
        dst[(size_t)(rowoff + n0 + ty + 8 * i) * Cc + k0 + tx] =
            __float2half_rn(t[tx][ty + 8 * i]);
}

__global__ void rope_table_kernel() {
    const int i = blockIdx.x * blockDim.x + threadIdx.x;
    if (i >= Tt * 64) return;
    const int t = i >> 6, f = i & 63;
    double inv = exp(-(double)f * 0.14391156831212787);  // ln(10000)/64
    double a = (double)t * inv;
    g_rope[i] = make_float2((float)sin(a), (float)cos(a));
}

// in-place rope on fused fp16 QKV (q and k columns only)
__global__ void rope_f16(__half* __restrict__ QKV) {
    const int idx = blockIdx.x * blockDim.x + threadIdx.x;
    const int nq = MROWS * NH * 64;
    const int nk = MROWS * NKV * 64;
    if (idx >= nq + nk) return;
    int f, bt, col;
    if (idx < nq) {
        f = idx & 63;
        int h = (idx >> 6) & (NH - 1);
        bt = idx >> 10;
        col = h * HD + f;
    } else {
        int k = idx - nq;
        f = k & 63;
        int h = (k >> 6) & (NKV - 1);
        bt = k >> 8;
        col = 2048 + h * HD + f;
    }
    const float2 sc = g_rope[(bt & (Tt - 1)) * 64 + f];
    const size_t base = (size_t)bt * NALL + col;
    const float x1 = __half2float(QKV[base]);
    const float x2 = __half2float(QKV[base + 64]);
    QKV[base]      = __float2half_rn(x1 * sc.y - x2 * sc.x);
    QKV[base + 64] = __float2half_rn(x2 * sc.y + x1 * sc.x);
}

// ------------------------- single-term fp16 HMMA GEMM -----------------------
// C[M,N] = A * B^T ; A [M,K] fp16 K-contig, B [N,K] fp16 K-contig.
// CTA tile 128x128, K-chunk 64 (128B rows, SW128), 3-stage cp.async pipeline.
#define GSMEM (3 * 32768 + 128)
template <typename OutT>
__global__ __launch_bounds__(256, 2) void gemm_f16(
    const __half* __restrict__ A, const __half* __restrict__ Bm,
    OutT* __restrict__ C, int Cstride, int Kdim)
{
    extern __shared__ char smraw[];
    const uint32_t sb = (smem_u32(smraw) + 127) & ~127u;
    const int tid = threadIdx.x;
    const int lane = tid & 31, wid = tid >> 5;
    const int wm = wid >> 1, wn = wid & 1;
    const int bm = blockIdx.y * 128, bn = blockIdx.x * 128;

    float acc[2][8][4];
#pragma unroll
    for (int i = 0; i < 2; i++)
#pragma unroll
        for (int t = 0; t < 8; t++)
#pragma unroll
            for (int e = 0; e < 4; e++) acc[i][t][e] = 0.0f;

    const int nch = Kdim >> 6;

    auto prefetch = [&](int ch) {
        const uint32_t st = sb + (ch % 3) * 32768;
        const int kc = ch << 6;
#pragma unroll
        for (int q = 0; q < 4; q++) {
            int idx = tid + q * 256;
            int r = idx >> 3, u = idx & 7;
            uint32_t so = swz128((uint32_t)(r * 128 + u * 16));
            cp16(st + so,         A  + (size_t)(bm + r) * Kdim + kc + u * 8);
            cp16(st + 16384 + so, Bm + (size_t)(bn + r) * Kdim + kc + u * 8);
        }
        CP_COMMIT();
    };

    prefetch(0);
    prefetch(1);
    const uint32_t arow = wm * 32 + (lane & 15);
    const uint32_t acb  = ((uint32_t)(lane >> 4)) << 4;
    const uint32_t brow = wn * 64 + (lane & 7) + (((uint32_t)(lane >> 4)) << 3);
    const uint32_t bcb  = (((uint32_t)(lane >> 3)) & 1u) << 4;

    for (int ch = 0; ch < nch; ch++) {
        if (ch + 2 < nch) { prefetch(ch + 2); cp_wait<2>(); }
        else if (ch + 1 < nch) cp_wait<1>();
        else cp_wait<0>();
        __syncthreads();
        const uint32_t st = sb + (ch % 3) * 32768;
#pragma unroll
        for (int s = 0; s < 4; s++) {
            const uint32_t kb = s * 32;
            uint32_t ah[2][4], bh[4][4];
#pragma unroll
            for (int i = 0; i < 2; i++)
                ldsm4(ah[i], st + swz128((arow + i * 16) * 128 + kb + acb));
#pragma unroll
            for (int j = 0; j < 4; j++)
                ldsm4(bh[j], st + 16384 + swz128((brow + j * 16) * 128 + kb + bcb));
#pragma unroll
            for (int i = 0; i < 2; i++)
#pragma unroll
                for (int t = 0; t < 8; t++)
                    mma16816h(acc[i][t], ah[i], &bh[t >> 1][(t & 1) * 2]);
        }
        __syncthreads();
    }

#pragma unroll
    for (int i = 0; i < 2; i++) {
        const int r0 = bm + wm * 32 + i * 16 + (lane >> 2);
#pragma unroll
        for (int t = 0; t < 8; t++) {
            const int c = bn + wn * 64 + t * 8 + (lane & 3) * 2;
            if constexpr (sizeof(OutT) == 2) {
                *(__half2*)(C + (size_t)r0 * Cstride + c) =
                    __floats2half2_rn(acc[i][t][0], acc[i][t][1]);
                *(__half2*)(C + (size_t)(r0 + 8) * Cstride + c) =
                    __floats2half2_rn(acc[i][t][2], acc[i][t][3]);
            } else {
                *(float2*)(C + (size_t)r0 * Cstride + c) =
                    make_float2(acc[i][t][0], acc[i][t][1]);
                *(float2*)(C + (size_t)(r0 + 8) * Cstride + c) =
                    make_float2(acc[i][t][2], acc[i][t][3]);
            }
        }
    }
}

// ------------------------- fp16 HMMA flash attention -----------------------
#define SQ  0
#define SK  32768
#define SV  65536
#define SP  98304
#define SRED 131072
#define ATT_SMEM (SRED + 896 * 4)

__global__ __launch_bounds__(256) void attn_hmma(
    const __half* __restrict__ QKV, __half* __restrict__ Oh)
{
    extern __shared__ char smraw[];
    const uint32_t sb = smem_u32(smraw);
    float* row_m = (float*)(smraw + SRED);
    float* row_l = row_m + 128;
    float* row_c = row_l + 128;
    float* pmax  = row_c + 128;   // [2][128]
    float* psum  = pmax + 256;    // [2][128]

    const int tid = threadIdx.x, lane = tid & 31, wid = tid >> 5;
    const int wm = wid >> 1, wn = wid & 1;
    const int qt = (int)gridDim.x - 1 - (int)blockIdx.x;   // heavy tiles first
    const int g = blockIdx.y, b = blockIdx.z;
    const int kvh = g & (NKV - 1);
    const int q0 = qt * 128;
    const size_t qrow = (size_t)(b * Tt + q0);

    auto loadQ = [&]() {
        const __half* gq = QKV + qrow * NALL + g * HD;
#pragma unroll
        for (int q = 0; q < 8; q++) {
            int idx = tid + q * 256;
            int r = idx >> 4, u = idx & 15;
            uint32_t so = ((uint32_t)(u >> 3) << 14) + swz128((uint32_t)(r * 128 + (u & 7) * 16));
            cp16(sb + SQ + so, gq + (size_t)r * NALL + u * 8);
        }
        CP_COMMIT();
    };
    auto loadK = [&](int kt) {
        const __half* gk = QKV + (size_t)(b * Tt + kt * 128) * NALL + 2048 + kvh * HD;
#pragma unroll
        for (int q = 0; q < 8; q++) {
            int idx = tid + q * 256;
            int r = idx >> 4, u = idx & 15;
            uint32_t so = ((uint32_t)(u >> 3) << 14) + swz128((uint32_t)(r * 128 + (u & 7) * 16));
            cp16(sb + SK + so, gk + (size_t)r * NALL + u * 8);
        }
        CP_COMMIT();
    };
    auto loadV = [&](int kt) {
        const __half* gv = QKV + (size_t)(b * Tt + kt * 128) * NALL + 2560 + kvh * HD;
#pragma unroll
        for (int q = 0; q < 8; q++) {
            int idx = tid + q * 256;
            int r = idx >> 4, u = idx & 15;
            uint32_t so = ((uint32_t)(u >> 3) << 14) + swz128((uint32_t)(r * 128 + (u & 7) * 16));
            cp16(sb + SV + so, gv + (size_t)r * NALL + u * 8);
        }
        CP_COMMIT();
    };

    loadQ();
    loadK(0);
    if (tid < 128) { row_m[tid] = -INFINITY; row_l[tid] = 0.0f; }

    float o[2][8][4];
#pragma unroll
    for (int i = 0; i < 2; i++)
#pragma unroll
        for (int t = 0; t < 8; t++)
#pragma unroll
            for (int e = 0; e < 4; e++) o[i][t][e] = 0.0f;

    const float pre = 0.08838834764831843f * 0.02f;  // (1/sqrt(128)) / 50

    for (int kt = 0; kt <= qt; kt++) {
        __syncthreads();                 // (a) prev PV readers of sV/sP done
        loadV(kt);
        cp_wait<1>();                    // Q + K(kt) arrived
        __syncthreads();                 // (b)

        // ---- S = Q K^T
        float s[2][8][4];
#pragma unroll
        for (int i = 0; i < 2; i++)
#pragma unroll
            for (int t = 0; t < 8; t++)
#pragma unroll
                for (int e = 0; e < 4; e++) s[i][t][e] = 0.0f;

#pragma unroll
        for (int ks = 0; ks < 8; ks++) {
            uint32_t ah[2][4];
#pragma unroll
            for (int i = 0; i < 2; i++) {
                uint32_t c = ks * 32 + ((uint32_t)(lane >> 4) << 4);
                uint32_t row = wm * 32 + i * 16 + (lane & 15);
                uint32_t off = ((c >> 7) << 14) + swz128(row * 128 + (c & 127));
                ldsm4(ah[i], sb + SQ + off);
            }
#pragma unroll
            for (int jt = 0; jt < 4; jt++) {
                uint32_t bh[4];
                uint32_t c = ks * 32 + (((uint32_t)(lane >> 3) & 1u) << 4);
                uint32_t j = wn * 64 + jt * 16 + (lane & 7) + ((uint32_t)(lane >> 4) << 3);
                uint32_t off = ((c >> 7) << 14) + swz128(j * 128 + (c & 127));
                ldsm4(bh, sb + SK + off);
#pragma unroll
                for (int i = 0; i < 2; i++)
#pragma unroll
                    for (int sub = 0; sub < 2; sub++)
                        mma16816h(s[i][jt * 2 + sub], ah[i], bh + sub * 2);
            }
        }

        // ---- softcap (poly tanh) + causal mask + row-max partials
        const bool diag = (kt == qt);
        float rmx[2][2] = {{-INFINITY, -INFINITY}, {-INFINITY, -INFINITY}};
#pragma unroll
        for (int i = 0; i < 2; i++)
#pragma unroll
            for (int t = 0; t < 8; t++)
#pragma unroll
                for (int e = 0; e < 4; e++) {
                    float x = s[i][t][e] * pre;
                    float x2 = x * x;
                    float th = x * (1.0f + x2 * (-0.33333333f + x2 * (0.13333333f - 0.05396825f * x2)));
                    float v = 50.0f * th;
                    if (diag) {
                        int r  = wm * 32 + i * 16 + (lane >> 2) + ((e >> 1) << 3);
                        int cc = wn * 64 + t * 8 + ((lane & 3) << 1) + (e & 1);
                        if (cc > r) v = -1e30f;
                    }
                    s[i][t][e] = v;
                    rmx[i][e >> 1] = fmaxf(rmx[i][e >> 1], v);
                }
#pragma unroll
        for (int i = 0; i < 2; i++)
#pragma unroll
            for (int h = 0; h < 2; h++) {
                float m = rmx[i][h];
                m = fmaxf(m, __shfl_xor_sync(0xffffffffu, m, 1));
                m = fmaxf(m, __shfl_xor_sync(0xffffffffu, m, 2));
                if ((lane & 3) == 0)
                    pmax[wn * 128 + wm * 32 + i * 16 + h * 8 + (lane >> 2)] = m;
            }
        __syncthreads();                 // (c) sK consumed; pmax visible

        if (kt < qt) loadK(kt + 1);      // prefetch next K

        if (tid < 128) {
            float mo = row_m[tid];
            float mn = fmaxf(mo, fmaxf(pmax[tid], pmax[128 + tid]));
            row_m[tid] = mn;
            row_c[tid] = __expf(mo - mn);
        }
        __syncthreads();                 // (d) row_m/row_c visible

        // ---- p = exp(s - m) -> fp16 sP; row-sums; rescale O
        float rsum[2][2] = {{0.f, 0.f}, {0.f, 0.f}};
#pragma unroll
        for (int i = 0; i < 2; i++)
#pragma unroll
            for (int h = 0; h < 2; h++) {
                int r = wm * 32 + i * 16 + h * 8 + (lane >> 2);
                float mr = row_m[r];
                float cr = row_c[r];
#pragma unroll
                for (int t = 0; t < 8; t++) {
                    float p0 = __expf(s[i][t][h * 2 + 0] - mr);
                    float p1 = __expf(s[i][t][h * 2 + 1] - mr);
                    rsum[i][h] += p0 + p1;
                    uint32_t cb = (uint32_t)(t * 8 + ((lane & 3) << 1)) * 2;
                    uint32_t off = ((uint32_t)wn << 14) + swz128((uint32_t)r * 128 + cb);
                    *(__half2*)(smraw + SP + off) = __floats2half2_rn(p0, p1);
                    o[i][t][h * 2 + 0] *= cr;
                    o[i][t][h * 2 + 1] *= cr;
                }
            }
#pragma unroll
        for (int i = 0; i < 2; i++)
#pragma unroll
            for (int h = 0; h < 2; h++) {
                float sv = rsum[i][h];
                sv += __shfl_xor_sync(0xffffffffu, sv, 1);
                sv += __shfl_xor_sync(0xffffffffu, sv, 2);
                if ((lane & 3) == 0)
                    psum[wn * 128 + wm * 32 + i * 16 + h * 8 + (lane >> 2)] = sv;
            }
        if (kt < qt) cp_wait<1>();       // V(kt) done
        else         cp_wait<0>();
        __syncthreads();                 // (e) sV + sP + psum visible
        if (tid < 128)
            row_l[tid] = row_l[tid] * row_c[tid] + psum[tid] + psum[128 + tid];

        // ---- O += P V
#pragma unroll
        for (int ks = 0; ks < 8; ks++) {
            uint32_t ph[2][4];
#pragma unroll
            for (int i = 0; i < 2; i++) {
                uint32_t c = ks * 32 + ((uint32_t)(lane >> 4) << 4);
                uint32_t row = wm * 32 + i * 16 + (lane & 15);
                uint32_t off = ((c >> 7) << 14) + swz128(row * 128 + (c & 127));
                ldsm4(ph[i], sb + SP + off);
            }
#pragma unroll
            for (int dt = 0; dt < 4; dt++) {
                uint32_t vh[4];
                uint32_t dbase = wn * 64 + dt * 16 + ((uint32_t)(lane >> 4) << 3);
                uint32_t j = ks * 16 + (lane & 15);
                uint32_t off = ((dbase >> 6) << 14) + swz128(j * 128 + (dbase & 63) * 2);
                ldsm4t(vh, sb + SV + off);
#pragma unroll
                for (int i = 0; i < 2; i++)
#pragma unroll
                    for (int sub = 0; sub < 2; sub++)
                        mma16816h(o[i][dt * 2 + sub], ph[i], vh + sub * 2);
            }
        }
    }

    __syncthreads();   // row_l final visible

    // ---- epilogue: normalize, write O fp16
#pragma unroll
    for (int i = 0; i < 2; i++)
#pragma unroll
        for (int h = 0; h < 2; h++) {
            int r = wm * 32 + i * 16 + h * 8 + (lane >> 2);
            float inv = 1.0f / row_l[r];
            size_t gro = (qrow + r) * QDIM + g * HD;
#pragma unroll
            for (int t = 0; t < 8; t++) {
                int cc = wn * 64 + t * 8 + ((lane & 3) << 1);
                *(__half2*)(Oh + gro + cc) = __floats2half2_rn(
                    o[i][t][h * 2 + 0] * inv, o[i][t][h * 2 + 1] * inv);
            }
        }
}

// ---------------------------------------------------------------------------
extern "C" void kernel_launch(void* const* d_in, const int* in_sizes, int n_in,
                              void* d_out, int out_size)
{
    const float* x  = (const float*)d_in[0];
    const float* wq = (const float*)d_in[2];
    const float* wk = (const float*)d_in[3];
    const float* wv = (const float*)d_in[4];
    const float* wo = (const float*)d_in[5];
    float* out = (float*)d_out;

    __half *xh, *qkvh, *oh, *wallT, *woT;
    cudaGetSymbolAddress((void**)&xh, g_xh);
    cudaGetSymbolAddress((void**)&qkvh, g_QKVh);
    cudaGetSymbolAddress((void**)&oh, g_Oh);
    cudaGetSymbolAddress((void**)&wallT, g_wAllT);
    cudaGetSymbolAddress((void**)&woT, g_woT);

    // ---- prep
    {
        int n4 = MROWS * Cc / 4;
        to_f16<<<(n4 + 255) / 256, 256>>>(x, xh, n4);
    }
    transpose_f16_all<<<dim3(QDIM / 32, Cc / 32, 4), dim3(32, 8)>>>(
        wq, wk, wv, wo, wallT, woT);
    rope_table_kernel<<<(Tt * 64 + 255) / 256, 256>>>();

    // ---- fused QKV projection (fp16 HMMA) -> fp16 QKV
    cudaFuncSetAttribute(gemm_f16<__half>, cudaFuncAttributeMaxDynamicSharedMemorySize, GSMEM);
    cudaFuncSetAttribute(gemm_f16<float>, cudaFuncAttributeMaxDynamicSharedMemorySize, GSMEM);
    gemm_f16<__half><<<dim3(NALL / 128, MROWS / 128), 256, GSMEM>>>(
        xh, wallT, qkvh, NALL, Cc);

    // ---- rope in-place on q/k columns
    {
        const int pairs = MROWS * (NH + NKV) * 64;
        rope_f16<<<(pairs + 255) / 256, 256>>>(qkvh);
    }

    // ---- attention (fp16 HMMA, reads strided from fused QKV)
    cudaFuncSetAttribute(attn_hmma, cudaFuncAttributeMaxDynamicSharedMemorySize, ATT_SMEM);
    attn_hmma<<<dim3(Tt / 128, NH, Bb), 256, ATT_SMEM>>>(qkvh, oh);

    // ---- output projection (fp16 HMMA) -> fp32 out
    gemm_f16<float><<<dim3(QDIM / 128, MROWS / 128), 256, GSMEM>>>(
        oh, woT, out, QDIM, Cc);
}